// round 11
// baseline (speedup 1.0000x reference)
#include <cuda_runtime.h>
#include <cuda_fp16.h>
#include <cstdint>

// ---------------------------------------------------------------------------
// Problem constants
// ---------------------------------------------------------------------------
#define BATCH   8
#define CH      256
#define HW      16384
#define IMG     (CH * HW)
#define GROUPS  32
#define GSZ     (CH / GROUPS)
#define NPIX    64
#define EPS     1e-5f

// g_qraw/g_kraw: fp16, WINDOW-TILED pixel layout within each channel:
//   px' = window_id * 64 + (y&7)*8 + (x&7),  window_id = (y>>3)*16 + (x>>3)
static __device__ __half g_qraw[(size_t)BATCH * IMG];
static __device__ __half g_kraw[(size_t)BATCH * IMG];
static __device__ float g_mean[2 * BATCH * GROUPS];
static __device__ float g_rstd[2 * BATCH * GROUPS];
// Pre-permuted fp16 A fragments (half2 k-pairs, m16n8k16 layout)
static __device__ uint32_t g_afragh[65536];
// per-(tensor,batch,group) x per-pixel-tile partial (sum, sumsq)
static __device__ float g_psum[512 * 256];

// ---------------------------------------------------------------------------
// helpers
// ---------------------------------------------------------------------------
__device__ __forceinline__ uint32_t pack_h2(float x, float y) {
    __half2 h = __float22half2_rn(make_float2(x, y));
    return *(uint32_t*)&h;
}
__device__ __forceinline__ float4 h4_to_f4(uint2 v) {
    float2 a = __half22float2(*(__half2*)&v.x);
    float2 b = __half22float2(*(__half2*)&v.y);
    return make_float4(a.x, a.y, b.x, b.y);
}

__device__ __forceinline__ void mmaf16(float d[4], const uint32_t a[4],
                                       uint32_t b0, uint32_t b1) {
    asm volatile(
        "mma.sync.aligned.m16n8k16.row.col.f32.f16.f16.f32 "
        "{%0,%1,%2,%3}, {%4,%5,%6,%7}, {%8,%9}, {%0,%1,%2,%3};"
        : "+f"(d[0]), "+f"(d[1]), "+f"(d[2]), "+f"(d[3])
        : "r"(a[0]), "r"(a[1]), "r"(a[2]), "r"(a[3]), "r"(b0), "r"(b1));
}

__device__ __forceinline__ uint32_t smem_u32(const void* p) {
    uint32_t a;
    asm("{ .reg .u64 t; cvta.to.shared.u64 t, %1; cvt.u32.u64 %0, t; }"
        : "=r"(a) : "l"(p));
    return a;
}

__device__ __forceinline__ void cpa16(uint32_t dst, const void* src) {
    asm volatile("cp.async.cg.shared.global [%0], [%1], 16;"
                 :: "r"(dst), "l"(src));
}
#define CPA_COMMIT() asm volatile("cp.async.commit_group;" ::: "memory")
#define CPA_WAIT(N)  asm volatile("cp.async.wait_group %0;" :: "n"(N) : "memory")

// ---------------------------------------------------------------------------
// Kernel 0: build fragment-ordered fp16 A operand (half2 k-pairs).
// ---------------------------------------------------------------------------
__global__ void __launch_bounds__(256) prep_afrag(
    const float* __restrict__ wq, const float* __restrict__ wk)
{
    int idx = blockIdx.x * 256 + threadIdx.x;   // 0..65535
    int reg   = idx & 3;
    int lane  = (idx >> 2) & 31;
    int ks    = (idx >> 7) & 1;
    int mbg   = (idx >> 8) & 7;
    int chunk = (idx >> 11) & 7;
    int mt    = (idx >> 14) & 1;
    int t     = (idx >> 15) & 1;

    int m  = mt * 128 + mbg * 16 + (reg & 1) * 8 + (lane >> 2);
    int kp = (lane & 3) + ((reg >> 1) & 1) * 4;
    int k  = chunk * 32 + ks * 16 + kp * 2;
    const float* W = t ? wk : wq;
    g_afragh[idx] = pack_h2(W[m * CH + k], W[m * CH + k + 1]);
}

// ---------------------------------------------------------------------------
// Kernel 1: projection GEMM via fp16 m16n8k16 + fused GroupNorm partials.
// (unchanged from R10)
// ---------------------------------------------------------------------------
#define BH_ST 136

__global__ void __launch_bounds__(256, 2) proj_mma(
    const float* __restrict__ xlo, const float* __restrict__ xhi)
{
    __shared__ uint32_t sA[4096];     // A0 @0, A1 @2048
    __shared__ uint32_t sB[4352];     // B0 @0, B1 @2176
    const uint32_t aBase = smem_u32(sA);

    const int tid  = threadIdx.x;
    const int wid  = tid >> 5;
    const int lane = tid & 31;

    const int mt = blockIdx.x;
    const int tz = blockIdx.z;
    const float* X = tz ? xhi : xlo;
    __half*      Y = tz ? g_kraw : g_qraw;

    const int bb = blockIdx.y >> 7;
    const int yrow = blockIdx.y & 127;
    const int p0 = yrow << 7;
    const int m0 = mt << 7;

    const float* Xb = X + (size_t)bb * IMG + p0;
    const uint32_t* Agh = g_afragh + (size_t)(tz * 2 + mt) * 16384;

    const int wm = wid >> 2;
    const int wn = wid & 3;

    const int kp = tid >> 4;          // 0..15
    const int nq = (tid & 15) * 8;    // 0..120

    float acc[4][4][4];
#pragma unroll
    for (int i = 0; i < 4; i++)
#pragma unroll
        for (int j = 0; j < 4; j++)
#pragma unroll
            for (int r = 0; r < 4; r++) acc[i][j][r] = 0.f;

    float4 b00, b01, b10, b11;
    {
        const float* r0 = Xb + (size_t)(2 * kp) * HW + nq;
        b00 = *(const float4*)(r0);
        b01 = *(const float4*)(r0 + 4);
        b10 = *(const float4*)(r0 + HW);
        b11 = *(const float4*)(r0 + HW + 4);
    }
    {
        uint4 t0, t1;
        t0.x = pack_h2(b00.x, b10.x); t0.y = pack_h2(b00.y, b10.y);
        t0.z = pack_h2(b00.z, b10.z); t0.w = pack_h2(b00.w, b10.w);
        t1.x = pack_h2(b01.x, b11.x); t1.y = pack_h2(b01.y, b11.y);
        t1.z = pack_h2(b01.z, b11.z); t1.w = pack_h2(b01.w, b11.w);
        *(uint4*)&sB[kp * BH_ST + nq]     = t0;
        *(uint4*)&sB[kp * BH_ST + nq + 4] = t1;
    }
#pragma unroll
    for (int i = 0; i < 2; i++) {
        int idx = i * 256 + tid;
        cpa16(aBase + idx * 16, Agh + idx * 4);
    }
    CPA_COMMIT();

#pragma unroll 1
    for (int c = 0; c < 8; c++) {
        const int buf = c & 1;
        CPA_WAIT(0);
        __syncthreads();

        if (c < 7) {
            const float* r0 = Xb + (size_t)((c + 1) * 32 + 2 * kp) * HW + nq;
            b00 = *(const float4*)(r0);
            b01 = *(const float4*)(r0 + 4);
            b10 = *(const float4*)(r0 + HW);
            b11 = *(const float4*)(r0 + HW + 4);
        }

        const uint32_t* Ab = sA + buf * 2048;
        const uint32_t* Bb = sB + buf * 2176;

#pragma unroll
        for (int ks = 0; ks < 2; ks++) {
            uint32_t afr[4][4];
#pragma unroll
            for (int mb = 0; mb < 4; mb++) {
                int mbg = wm * 4 + mb;
                *(uint4*)afr[mb] =
                    *(const uint4*)&Ab[(mbg * 2 + ks) * 128 + lane * 4];
            }
            const int krow = ks * 8 + (lane & 3);
            const int ncol = wn * 32 + (lane >> 2);
#pragma unroll
            for (int nb = 0; nb < 4; nb++) {
                uint32_t b0 = Bb[krow * BH_ST + ncol + nb * 8];
                uint32_t b1 = Bb[(krow + 4) * BH_ST + ncol + nb * 8];
#pragma unroll
                for (int mb = 0; mb < 4; mb++)
                    mmaf16(acc[mb][nb], afr[mb], b0, b1);
            }
        }

        if (c < 7) {
            const int nb_ = buf ^ 1;
            uint4 t0, t1;
            t0.x = pack_h2(b00.x, b10.x); t0.y = pack_h2(b00.y, b10.y);
            t0.z = pack_h2(b00.z, b10.z); t0.w = pack_h2(b00.w, b10.w);
            t1.x = pack_h2(b01.x, b11.x); t1.y = pack_h2(b01.y, b11.y);
            t1.z = pack_h2(b01.z, b11.z); t1.w = pack_h2(b01.w, b11.w);
            *(uint4*)&sB[nb_ * 2176 + kp * BH_ST + nq]     = t0;
            *(uint4*)&sB[nb_ * 2176 + kp * BH_ST + nq + 4] = t1;
#pragma unroll
            for (int i = 0; i < 2; i++) {
                int idx = i * 256 + tid;
                cpa16(aBase + (nb_ * 2048 + idx * 4) * 4,
                      Agh + (c + 1) * 2048 + idx * 4);
            }
            CPA_COMMIT();
        }
    }

    // ---- fused GroupNorm partial statistics ----
    __shared__ float red[16][4][2];
#pragma unroll
    for (int mb = 0; mb < 4; mb++) {
        float sE = 0.f, qE = 0.f, sO_ = 0.f, qO = 0.f;
#pragma unroll
        for (int nb = 0; nb < 4; nb++) {
            sE += acc[mb][nb][0] + acc[mb][nb][1];
            qE += acc[mb][nb][0] * acc[mb][nb][0] + acc[mb][nb][1] * acc[mb][nb][1];
            sO_ += acc[mb][nb][2] + acc[mb][nb][3];
            qO += acc[mb][nb][2] * acc[mb][nb][2] + acc[mb][nb][3] * acc[mb][nb][3];
        }
#pragma unroll
        for (int off = 16; off; off >>= 1) {
            sE += __shfl_xor_sync(0xffffffffu, sE, off);
            qE += __shfl_xor_sync(0xffffffffu, qE, off);
            sO_ += __shfl_xor_sync(0xffffffffu, sO_, off);
            qO += __shfl_xor_sync(0xffffffffu, qO, off);
        }
        if (lane == 0) {
            int gl = wm * 8 + mb * 2;
            red[gl][wn][0] = sE;     red[gl][wn][1] = qE;
            red[gl + 1][wn][0] = sO_; red[gl + 1][wn][1] = qO;
        }
    }
    __syncthreads();
    if (tid < 32) {
        int gl = tid >> 1, sq = tid & 1;
        float v = red[gl][0][sq] + red[gl][1][sq] + red[gl][2][sq] + red[gl][3][sq];
        g_psum[((size_t)((tz * 8 + bb) * 32) + mt * 16 + gl) * 256 + yrow * 2 + sq] = v;
    }

    // ---- epilogue: fp16 window-tiled store ----
    const int base2 = (yrow >> 3) * 1024 + (yrow & 7) * 8;
    __half* Yb = Y + (size_t)bb * IMG + base2;
    const int rl = lane >> 2;
    const int cl = (lane & 3) * 2;
#pragma unroll
    for (int mb = 0; mb < 4; mb++) {
        int mrow = m0 + wm * 64 + mb * 16 + rl;
#pragma unroll
        for (int nb = 0; nb < 4; nb++) {
            int noff = (wn * 4 + nb) * 64 + cl;
            __half2 v0 = __floats2half2_rn(acc[mb][nb][0], acc[mb][nb][1]);
            __half2 v1 = __floats2half2_rn(acc[mb][nb][2], acc[mb][nb][3]);
            *(__half2*)(Yb + (size_t)mrow * HW + noff)       = v0;
            *(__half2*)(Yb + (size_t)(mrow + 8) * HW + noff) = v1;
        }
    }
}

// ---------------------------------------------------------------------------
// Kernel 2: GroupNorm stats finalize.
// ---------------------------------------------------------------------------
__global__ void __launch_bounds__(128) stats_finalize()
{
    const int id  = blockIdx.x;
    const int tid = threadIdx.x;
    const float* p = g_psum + (size_t)id * 256;

    __shared__ float rs[128], rq[128];
    rs[tid] = p[tid * 2];
    rq[tid] = p[tid * 2 + 1];
    __syncthreads();
    for (int o = 64; o; o >>= 1) {
        if (tid < o) { rs[tid] += rs[tid + o]; rq[tid] += rq[tid + o]; }
        __syncthreads();
    }
    if (tid == 0) {
        const float invN = 1.f / (float)(GSZ * HW);
        float m   = rs[0] * invN;
        float var = rq[0] * invN - m * m;
        g_mean[id] = m;
        g_rstd[id] = rsqrtf(var + EPS);
    }
}

// ---------------------------------------------------------------------------
// Kernel 3: windowed attention. Phase S as R10; PV rewritten with
// warp-private sO tiles: zero __syncthreads in PV, only __syncwarp.
// ---------------------------------------------------------------------------
#define QP_ST 72
#define SP_ST 68
#define PH_ST 36
#define KV_ST 36
#define AT_QP   0
#define AT_KP   1152
#define AT_PH   2304
#define AT_KV   4608
#define AT_PMAX 13824
#define AT_PSUM 13952
#define AT_SMEM_BYTES (14080 * 4)

__global__ void __launch_bounds__(256) attn_mma(
    const float* __restrict__ xlo, float* __restrict__ outp,
    const float* __restrict__ gq, const float* __restrict__ bq,
    const float* __restrict__ gk, const float* __restrict__ bk)
{
    extern __shared__ __align__(16) uint32_t sm[];
    uint32_t* sQp = sm + AT_QP;
    uint32_t* sKp = sm + AT_KP;
    uint32_t* sPh = sm + AT_PH;
    uint32_t* sKv = sm + AT_KV;
    float*    pmax = (float*)(sm + AT_PMAX);
    float*    psum = (float*)(sm + AT_PSUM);

    const int tid  = threadIdx.x;
    const int wid  = tid >> 5;
    const int lane = tid & 31;

    const int bb  = blockIdx.x >> 8;
    const int wnd = blockIdx.x & 255;
    const int base_px = ((wnd >> 4) << 3) * 128 + ((wnd & 15) << 3);
    const int wbase = wnd * 64;

    const __half* qb = g_qraw + (size_t)bb * IMG;
    const __half* kb = g_kraw + (size_t)bb * IMG;

    const int wm = wid & 3;
    const int wn = wid >> 2;

    const int p_  = tid >> 4;
    const int pg  = (tid & 15) * 4;

    float acc[4][4];
#pragma unroll
    for (int i = 0; i < 4; i++)
#pragma unroll
        for (int j = 0; j < 4; j++) acc[i][j] = 0.f;

    uint2 q0h, q1h, k0h, k1h;
    {
        const size_t ga0 = (size_t)(2 * p_) * HW + wbase + pg;
        q0h = *(const uint2*)(qb + ga0);
        q1h = *(const uint2*)(qb + ga0 + HW);
        k0h = *(const uint2*)(kb + ga0);
        k1h = *(const uint2*)(kb + ga0 + HW);
    }

    // ================= Phase S =================
#pragma unroll 1
    for (int cc = 0; cc < 8; cc++) {
        const int c0 = cc * 32 + 2 * p_;
        const int g  = c0 >> 3;
        float4 q0 = h4_to_f4(q0h), q1 = h4_to_f4(q1h);
        float4 k0 = h4_to_f4(k0h), k1 = h4_to_f4(k1h);
        uint4 tq, tk;
        uint2 kv0, kv1;
        {
            float rq_ = g_rstd[bb * 32 + g], mq_ = g_mean[bb * 32 + g];
            float a0 = rq_ * gq[c0],     d0 = fmaf(-mq_, a0, bq[c0]);
            float a1 = rq_ * gq[c0 + 1], d1 = fmaf(-mq_, a1, bq[c0 + 1]);
            tq.x = pack_h2(fmaf(q0.x, a0, d0), fmaf(q1.x, a1, d1));
            tq.y = pack_h2(fmaf(q0.y, a0, d0), fmaf(q1.y, a1, d1));
            tq.z = pack_h2(fmaf(q0.z, a0, d0), fmaf(q1.z, a1, d1));
            tq.w = pack_h2(fmaf(q0.w, a0, d0), fmaf(q1.w, a1, d1));
        }
        {
            float rk_ = g_rstd[256 + bb * 32 + g], mk_ = g_mean[256 + bb * 32 + g];
            float a0 = rk_ * gk[c0],     d0 = fmaf(-mk_, a0, bk[c0]);
            float a1 = rk_ * gk[c0 + 1], d1 = fmaf(-mk_, a1, bk[c0 + 1]);
            float f00 = fmaf(k0.x, a0, d0), f01 = fmaf(k0.y, a0, d0);
            float f02 = fmaf(k0.z, a0, d0), f03 = fmaf(k0.w, a0, d0);
            float f10 = fmaf(k1.x, a1, d1), f11 = fmaf(k1.y, a1, d1);
            float f12 = fmaf(k1.z, a1, d1), f13 = fmaf(k1.w, a1, d1);
            tk.x = pack_h2(f00, f10);
            tk.y = pack_h2(f01, f11);
            tk.z = pack_h2(f02, f12);
            tk.w = pack_h2(f03, f13);
            kv0 = make_uint2(pack_h2(f00, f01), pack_h2(f02, f03));
            kv1 = make_uint2(pack_h2(f10, f11), pack_h2(f12, f13));
        }

        if (cc < 7) {
            const size_t gan = (size_t)((cc + 1) * 32 + 2 * p_) * HW + wbase + pg;
            q0h = *(const uint2*)(qb + gan);
            q1h = *(const uint2*)(qb + gan + HW);
            k0h = *(const uint2*)(kb + gan);
            k1h = *(const uint2*)(kb + gan + HW);
        }

        if (cc) __syncthreads();

        *(uint4*)&sQp[p_ * QP_ST + pg] = tq;
        *(uint4*)&sKp[p_ * QP_ST + pg] = tk;
        *(uint2*)&sKv[(size_t)c0 * KV_ST + (pg >> 1)]       = kv0;
        *(uint2*)&sKv[(size_t)(c0 + 1) * KV_ST + (pg >> 1)] = kv1;
        __syncthreads();

#pragma unroll
        for (int ks = 0; ks < 2; ks++) {
            const int kp = ks * 8 + (lane & 3);
            const int mrow = wm * 16 + (lane >> 2);
            uint32_t a[4];
            a[0] = sQp[kp * QP_ST + mrow];
            a[1] = sQp[kp * QP_ST + mrow + 8];
            a[2] = sQp[(kp + 4) * QP_ST + mrow];
            a[3] = sQp[(kp + 4) * QP_ST + mrow + 8];
#pragma unroll
            for (int nb = 0; nb < 4; nb++) {
                const int ncol = wn * 32 + nb * 8 + (lane >> 2);
                uint32_t b0 = sKp[kp * QP_ST + ncol];
                uint32_t b1 = sKp[(kp + 4) * QP_ST + ncol];
                mmaf16(acc[nb], a, b0, b1);
            }
        }
    }

    // ================= register softmax =================
    const int rA = wm * 16 + (lane >> 2);
    const int rB = rA + 8;
    {
#pragma unroll
        for (int nb = 0; nb < 4; nb++)
#pragma unroll
            for (int r = 0; r < 4; r++) acc[nb][r] *= 0.0625f;

        float mA = acc[0][0], mB = acc[0][2];
#pragma unroll
        for (int nb = 0; nb < 4; nb++) {
            mA = fmaxf(mA, fmaxf(acc[nb][0], acc[nb][1]));
            mB = fmaxf(mB, fmaxf(acc[nb][2], acc[nb][3]));
        }
        mA = fmaxf(mA, __shfl_xor_sync(0xffffffffu, mA, 1));
        mA = fmaxf(mA, __shfl_xor_sync(0xffffffffu, mA, 2));
        mB = fmaxf(mB, __shfl_xor_sync(0xffffffffu, mB, 1));
        mB = fmaxf(mB, __shfl_xor_sync(0xffffffffu, mB, 2));
        __syncthreads();
        if ((lane & 3) == 0) {
            pmax[rA * 2 + wn] = mA;
            pmax[rB * 2 + wn] = mB;
        }
        __syncthreads();

        float MA = fmaxf(pmax[rA * 2], pmax[rA * 2 + 1]);
        float MB = fmaxf(pmax[rB * 2], pmax[rB * 2 + 1]);
        float sA = 0.f, sB = 0.f;
#pragma unroll
        for (int nb = 0; nb < 4; nb++) {
            acc[nb][0] = __expf(acc[nb][0] - MA);
            acc[nb][1] = __expf(acc[nb][1] - MA);
            acc[nb][2] = __expf(acc[nb][2] - MB);
            acc[nb][3] = __expf(acc[nb][3] - MB);
            sA += acc[nb][0] + acc[nb][1];
            sB += acc[nb][2] + acc[nb][3];
        }
        sA += __shfl_xor_sync(0xffffffffu, sA, 1);
        sA += __shfl_xor_sync(0xffffffffu, sA, 2);
        sB += __shfl_xor_sync(0xffffffffu, sB, 1);
        sB += __shfl_xor_sync(0xffffffffu, sB, 2);
        if ((lane & 3) == 0) {
            psum[rA * 2 + wn] = sA;
            psum[rB * 2 + wn] = sB;
        }
        __syncthreads();

        float invA = 1.f / (psum[rA * 2] + psum[rA * 2 + 1]);
        float invB = 1.f / (psum[rB * 2] + psum[rB * 2 + 1]);
#pragma unroll
        for (int nb = 0; nb < 4; nb++) {
            int pcol = wn * 16 + nb * 4 + (lane & 3);
            sPh[rA * PH_ST + pcol] = pack_h2(acc[nb][0] * invA, acc[nb][1] * invA);
            sPh[rB * PH_ST + pcol] = pack_h2(acc[nb][2] * invB, acc[nb][3] * invB);
        }
    }
    __syncthreads();   // sPh + reuse of sQp/sKp region as sO

    // ================= Phase PV — warp-private sO, no CTA barriers ========
    float* sO = (float*)sm;   // [32 ch][SP_ST px]; warp (wm,wn) owns
                              // ch in [wn*16, wn*16+16) x px in [wm*16, wm*16+16)

    // out/residual lane mapping (within the warp's own tile):
    const int pch = wn * 16 + (lane >> 1);       // channel-local 0..31
    const int pp1 = wm * 2 + (lane & 1);         // patch row 0..7
    const size_t gpix = (size_t)bb * IMG + base_px + pp1 * 128;

    float4 xR0, xR1;
    {
        const float* xp = xlo + gpix + (size_t)pch * HW;
        xR0 = *(const float4*)(xp);
        xR1 = *(const float4*)(xp + 4);
    }

#pragma unroll 1
    for (int cc = 0; cc < 8; cc++) {
        float acc2[2][4];
#pragma unroll
        for (int nb = 0; nb < 2; nb++)
#pragma unroll
            for (int r = 0; r < 4; r++) acc2[nb][r] = 0.f;

#pragma unroll
        for (int ks = 0; ks < 4; ks++) {
            const int jp = ks * 8 + (lane & 3);
            const int i0 = wm * 16 + (lane >> 2);
            uint32_t a[4];
            a[0] = sPh[i0 * PH_ST + jp];
            a[1] = sPh[(i0 + 8) * PH_ST + jp];
            a[2] = sPh[i0 * PH_ST + jp + 4];
            a[3] = sPh[(i0 + 8) * PH_ST + jp + 4];
#pragma unroll
            for (int nb = 0; nb < 2; nb++) {
                const int c = cc * 32 + wn * 16 + nb * 8 + (lane >> 2);
                uint32_t b0 = sKv[c * KV_ST + jp];
                uint32_t b1 = sKv[c * KV_ST + jp + 4];
                mmaf16(acc2[nb], a, b0, b1);
            }
        }

        __syncwarp();   // previous iteration's LDS-reads of this tile done
        {
            const int px = wm * 16 + (lane >> 2);
#pragma unroll
            for (int nb = 0; nb < 2; nb++) {
                const int chl = wn * 16 + nb * 8 + (lane & 3) * 2;
                sO[chl * SP_ST + px]           = acc2[nb][0];
                sO[(chl + 1) * SP_ST + px]     = acc2[nb][1];
                sO[chl * SP_ST + px + 8]       = acc2[nb][2];
                sO[(chl + 1) * SP_ST + px + 8] = acc2[nb][3];
            }
        }
        __syncwarp();   // tile visible within warp

        {
            const int so_base = pch * SP_ST + wm * 16 + (lane & 1) * 8;
            float4 o0 = *(const float4*)&sO[so_base];
            float4 o1 = *(const float4*)&sO[so_base + 4];
            o0.x += xR0.x; o0.y += xR0.y; o0.z += xR0.z; o0.w += xR0.w;
            o1.x += xR1.x; o1.y += xR1.y; o1.z += xR1.z; o1.w += xR1.w;
            float* op = outp + gpix + (size_t)(cc * 32 + pch) * HW;
            *(float4*)(op)     = o0;
            *(float4*)(op + 4) = o1;
            if (cc < 7) {
                const float* xp = xlo + gpix + (size_t)((cc + 1) * 32 + pch) * HW;
                xR0 = *(const float4*)(xp);
                xR1 = *(const float4*)(xp + 4);
            }
        }
    }
}

// ---------------------------------------------------------------------------
// Launcher
// ---------------------------------------------------------------------------
extern "C" void kernel_launch(void* const* d_in, const int* in_sizes, int n_in,
                              void* d_out, int out_size)
{
    const float* x_low  = (const float*)d_in[0];
    const float* x_high = (const float*)d_in[1];
    const float* wq     = (const float*)d_in[2];
    const float* wk     = (const float*)d_in[3];
    const float* gq     = (const float*)d_in[4];
    const float* bq     = (const float*)d_in[5];
    const float* gk     = (const float*)d_in[6];
    const float* bk     = (const float*)d_in[7];
    float* outp = (float*)d_out;

    prep_afrag<<<256, 256>>>(wq, wk);

    proj_mma<<<dim3(2, 1024, 2), 256>>>(x_low, x_high);

    stats_finalize<<<512, 128>>>();

    cudaFuncSetAttribute(attn_mma,
                         cudaFuncAttributeMaxDynamicSharedMemorySize,
                         AT_SMEM_BYTES);
    attn_mma<<<2048, 256, AT_SMEM_BYTES>>>(x_low, outp, gq, bq, gk, bk);
}

// round 12
// speedup vs baseline: 1.0920x; 1.0920x over previous
#include <cuda_runtime.h>
#include <cuda_fp16.h>
#include <cstdint>

// ---------------------------------------------------------------------------
// Problem constants
// ---------------------------------------------------------------------------
#define BATCH   8
#define CH      256
#define HW      16384
#define IMG     (CH * HW)
#define GROUPS  32
#define GSZ     (CH / GROUPS)
#define NPIX    64
#define EPS     1e-5f

// g_qraw/g_kraw: fp16, WINDOW-TILED pixel layout within each channel:
//   px' = window_id * 64 + (y&7)*8 + (x&7),  window_id = (y>>3)*16 + (x>>3)
static __device__ __half g_qraw[(size_t)BATCH * IMG];
static __device__ __half g_kraw[(size_t)BATCH * IMG];
static __device__ float g_mean[2 * BATCH * GROUPS];
static __device__ float g_rstd[2 * BATCH * GROUPS];
// Pre-permuted fp16 A fragments (half2 k-pairs, m16n8k16 layout)
static __device__ uint32_t g_afragh[65536];
// per-(tensor,batch,group) x per-pixel-tile partial (sum, sumsq)
static __device__ float g_psum[512 * 256];

// ---------------------------------------------------------------------------
// helpers
// ---------------------------------------------------------------------------
__device__ __forceinline__ uint32_t pack_h2(float x, float y) {
    __half2 h = __float22half2_rn(make_float2(x, y));
    return *(uint32_t*)&h;
}
__device__ __forceinline__ float4 h4_to_f4(uint2 v) {
    float2 a = __half22float2(*(__half2*)&v.x);
    float2 b = __half22float2(*(__half2*)&v.y);
    return make_float4(a.x, a.y, b.x, b.y);
}

__device__ __forceinline__ void mmaf16(float d[4], const uint32_t a[4],
                                       uint32_t b0, uint32_t b1) {
    asm volatile(
        "mma.sync.aligned.m16n8k16.row.col.f32.f16.f16.f32 "
        "{%0,%1,%2,%3}, {%4,%5,%6,%7}, {%8,%9}, {%0,%1,%2,%3};"
        : "+f"(d[0]), "+f"(d[1]), "+f"(d[2]), "+f"(d[3])
        : "r"(a[0]), "r"(a[1]), "r"(a[2]), "r"(a[3]), "r"(b0), "r"(b1));
}

__device__ __forceinline__ uint32_t smem_u32(const void* p) {
    uint32_t a;
    asm("{ .reg .u64 t; cvta.to.shared.u64 t, %1; cvt.u32.u64 %0, t; }"
        : "=r"(a) : "l"(p));
    return a;
}

__device__ __forceinline__ void cpa16(uint32_t dst, const void* src) {
    asm volatile("cp.async.cg.shared.global [%0], [%1], 16;"
                 :: "r"(dst), "l"(src));
}
#define CPA_COMMIT() asm volatile("cp.async.commit_group;" ::: "memory")
#define CPA_WAIT(N)  asm volatile("cp.async.wait_group %0;" :: "n"(N) : "memory")

// ---------------------------------------------------------------------------
// Kernel 0: build fragment-ordered fp16 A operand (half2 k-pairs).
// ---------------------------------------------------------------------------
__global__ void __launch_bounds__(256) prep_afrag(
    const float* __restrict__ wq, const float* __restrict__ wk)
{
    int idx = blockIdx.x * 256 + threadIdx.x;   // 0..65535
    int reg   = idx & 3;
    int lane  = (idx >> 2) & 31;
    int ks    = (idx >> 7) & 1;
    int mbg   = (idx >> 8) & 7;
    int chunk = (idx >> 11) & 7;
    int mt    = (idx >> 14) & 1;
    int t     = (idx >> 15) & 1;

    int m  = mt * 128 + mbg * 16 + (reg & 1) * 8 + (lane >> 2);
    int kp = (lane & 3) + ((reg >> 1) & 1) * 4;
    int k  = chunk * 32 + ks * 16 + kp * 2;
    const float* W = t ? wk : wq;
    g_afragh[idx] = pack_h2(W[m * CH + k], W[m * CH + k + 1]);
}

// ---------------------------------------------------------------------------
// Kernel 1: projection GEMM via fp16 m16n8k16 + fused GroupNorm partials.
// (unchanged from R10)
// ---------------------------------------------------------------------------
#define BH_ST 136

__global__ void __launch_bounds__(256, 2) proj_mma(
    const float* __restrict__ xlo, const float* __restrict__ xhi)
{
    __shared__ uint32_t sA[4096];     // A0 @0, A1 @2048
    __shared__ uint32_t sB[4352];     // B0 @0, B1 @2176
    const uint32_t aBase = smem_u32(sA);

    const int tid  = threadIdx.x;
    const int wid  = tid >> 5;
    const int lane = tid & 31;

    const int mt = blockIdx.x;
    const int tz = blockIdx.z;
    const float* X = tz ? xhi : xlo;
    __half*      Y = tz ? g_kraw : g_qraw;

    const int bb = blockIdx.y >> 7;
    const int yrow = blockIdx.y & 127;
    const int p0 = yrow << 7;
    const int m0 = mt << 7;

    const float* Xb = X + (size_t)bb * IMG + p0;
    const uint32_t* Agh = g_afragh + (size_t)(tz * 2 + mt) * 16384;

    const int wm = wid >> 2;
    const int wn = wid & 3;

    const int kp = tid >> 4;          // 0..15
    const int nq = (tid & 15) * 8;    // 0..120

    float acc[4][4][4];
#pragma unroll
    for (int i = 0; i < 4; i++)
#pragma unroll
        for (int j = 0; j < 4; j++)
#pragma unroll
            for (int r = 0; r < 4; r++) acc[i][j][r] = 0.f;

    float4 b00, b01, b10, b11;
    {
        const float* r0 = Xb + (size_t)(2 * kp) * HW + nq;
        b00 = *(const float4*)(r0);
        b01 = *(const float4*)(r0 + 4);
        b10 = *(const float4*)(r0 + HW);
        b11 = *(const float4*)(r0 + HW + 4);
    }
    {
        uint4 t0, t1;
        t0.x = pack_h2(b00.x, b10.x); t0.y = pack_h2(b00.y, b10.y);
        t0.z = pack_h2(b00.z, b10.z); t0.w = pack_h2(b00.w, b10.w);
        t1.x = pack_h2(b01.x, b11.x); t1.y = pack_h2(b01.y, b11.y);
        t1.z = pack_h2(b01.z, b11.z); t1.w = pack_h2(b01.w, b11.w);
        *(uint4*)&sB[kp * BH_ST + nq]     = t0;
        *(uint4*)&sB[kp * BH_ST + nq + 4] = t1;
    }
#pragma unroll
    for (int i = 0; i < 2; i++) {
        int idx = i * 256 + tid;
        cpa16(aBase + idx * 16, Agh + idx * 4);
    }
    CPA_COMMIT();

#pragma unroll 1
    for (int c = 0; c < 8; c++) {
        const int buf = c & 1;
        CPA_WAIT(0);
        __syncthreads();

        if (c < 7) {
            const float* r0 = Xb + (size_t)((c + 1) * 32 + 2 * kp) * HW + nq;
            b00 = *(const float4*)(r0);
            b01 = *(const float4*)(r0 + 4);
            b10 = *(const float4*)(r0 + HW);
            b11 = *(const float4*)(r0 + HW + 4);
        }

        const uint32_t* Ab = sA + buf * 2048;
        const uint32_t* Bb = sB + buf * 2176;

#pragma unroll
        for (int ks = 0; ks < 2; ks++) {
            uint32_t afr[4][4];
#pragma unroll
            for (int mb = 0; mb < 4; mb++) {
                int mbg = wm * 4 + mb;
                *(uint4*)afr[mb] =
                    *(const uint4*)&Ab[(mbg * 2 + ks) * 128 + lane * 4];
            }
            const int krow = ks * 8 + (lane & 3);
            const int ncol = wn * 32 + (lane >> 2);
#pragma unroll
            for (int nb = 0; nb < 4; nb++) {
                uint32_t b0 = Bb[krow * BH_ST + ncol + nb * 8];
                uint32_t b1 = Bb[(krow + 4) * BH_ST + ncol + nb * 8];
#pragma unroll
                for (int mb = 0; mb < 4; mb++)
                    mmaf16(acc[mb][nb], afr[mb], b0, b1);
            }
        }

        if (c < 7) {
            const int nb_ = buf ^ 1;
            uint4 t0, t1;
            t0.x = pack_h2(b00.x, b10.x); t0.y = pack_h2(b00.y, b10.y);
            t0.z = pack_h2(b00.z, b10.z); t0.w = pack_h2(b00.w, b10.w);
            t1.x = pack_h2(b01.x, b11.x); t1.y = pack_h2(b01.y, b11.y);
            t1.z = pack_h2(b01.z, b11.z); t1.w = pack_h2(b01.w, b11.w);
            *(uint4*)&sB[nb_ * 2176 + kp * BH_ST + nq]     = t0;
            *(uint4*)&sB[nb_ * 2176 + kp * BH_ST + nq + 4] = t1;
#pragma unroll
            for (int i = 0; i < 2; i++) {
                int idx = i * 256 + tid;
                cpa16(aBase + (nb_ * 2048 + idx * 4) * 4,
                      Agh + (c + 1) * 2048 + idx * 4);
            }
            CPA_COMMIT();
        }
    }

    // ---- fused GroupNorm partial statistics ----
    __shared__ float red[16][4][2];
#pragma unroll
    for (int mb = 0; mb < 4; mb++) {
        float sE = 0.f, qE = 0.f, sO_ = 0.f, qO = 0.f;
#pragma unroll
        for (int nb = 0; nb < 4; nb++) {
            sE += acc[mb][nb][0] + acc[mb][nb][1];
            qE += acc[mb][nb][0] * acc[mb][nb][0] + acc[mb][nb][1] * acc[mb][nb][1];
            sO_ += acc[mb][nb][2] + acc[mb][nb][3];
            qO += acc[mb][nb][2] * acc[mb][nb][2] + acc[mb][nb][3] * acc[mb][nb][3];
        }
#pragma unroll
        for (int off = 16; off; off >>= 1) {
            sE += __shfl_xor_sync(0xffffffffu, sE, off);
            qE += __shfl_xor_sync(0xffffffffu, qE, off);
            sO_ += __shfl_xor_sync(0xffffffffu, sO_, off);
            qO += __shfl_xor_sync(0xffffffffu, qO, off);
        }
        if (lane == 0) {
            int gl = wm * 8 + mb * 2;
            red[gl][wn][0] = sE;     red[gl][wn][1] = qE;
            red[gl + 1][wn][0] = sO_; red[gl + 1][wn][1] = qO;
        }
    }
    __syncthreads();
    if (tid < 32) {
        int gl = tid >> 1, sq = tid & 1;
        float v = red[gl][0][sq] + red[gl][1][sq] + red[gl][2][sq] + red[gl][3][sq];
        g_psum[((size_t)((tz * 8 + bb) * 32) + mt * 16 + gl) * 256 + yrow * 2 + sq] = v;
    }

    // ---- epilogue: fp16 window-tiled store ----
    const int base2 = (yrow >> 3) * 1024 + (yrow & 7) * 8;
    __half* Yb = Y + (size_t)bb * IMG + base2;
    const int rl = lane >> 2;
    const int cl = (lane & 3) * 2;
#pragma unroll
    for (int mb = 0; mb < 4; mb++) {
        int mrow = m0 + wm * 64 + mb * 16 + rl;
#pragma unroll
        for (int nb = 0; nb < 4; nb++) {
            int noff = (wn * 4 + nb) * 64 + cl;
            __half2 v0 = __floats2half2_rn(acc[mb][nb][0], acc[mb][nb][1]);
            __half2 v1 = __floats2half2_rn(acc[mb][nb][2], acc[mb][nb][3]);
            *(__half2*)(Yb + (size_t)mrow * HW + noff)       = v0;
            *(__half2*)(Yb + (size_t)(mrow + 8) * HW + noff) = v1;
        }
    }
}

// ---------------------------------------------------------------------------
// Kernel 2: GroupNorm stats finalize.
// ---------------------------------------------------------------------------
__global__ void __launch_bounds__(128) stats_finalize()
{
    const int id  = blockIdx.x;
    const int tid = threadIdx.x;
    const float* p = g_psum + (size_t)id * 256;

    __shared__ float rs[128], rq[128];
    rs[tid] = p[tid * 2];
    rq[tid] = p[tid * 2 + 1];
    __syncthreads();
    for (int o = 64; o; o >>= 1) {
        if (tid < o) { rs[tid] += rs[tid + o]; rq[tid] += rq[tid + o]; }
        __syncthreads();
    }
    if (tid == 0) {
        const float invN = 1.f / (float)(GSZ * HW);
        float m   = rs[0] * invN;
        float var = rq[0] * invN - m * m;
        g_mean[id] = m;
        g_rstd[id] = rsqrtf(var + EPS);
    }
}

// ---------------------------------------------------------------------------
// Kernel 3: windowed attention. R10 structure, but Phase S staging
// PING-PONGS between sm[0..2304) and sm[2304..4608) (sPh region, dead
// during S) -> ONE CTA barrier per chunk instead of two. PV identical to R10.
// smem layout (uint32 words):
//   S buffers  @0 and @2304 : each 16x72 Q + 16x72 K (half2 channel-pairs)
//   sPh        @2304 : 64x36  P half2 (written only after Phase S)
//   sKv        @4608 : 256x36 K half2 (pixel pairs), persistent
//   pmax @13824, psum @13952 ; sO (PV) reuses @0 region [32][68] f32
// ---------------------------------------------------------------------------
#define QP_ST 72
#define SP_ST 68
#define PH_ST 36
#define KV_ST 36
#define AT_PH   2304
#define AT_KV   4608
#define AT_PMAX 13824
#define AT_PSUM 13952
#define AT_SMEM_BYTES (14080 * 4)

__global__ void __launch_bounds__(256) attn_mma(
    const float* __restrict__ xlo, float* __restrict__ outp,
    const float* __restrict__ gq, const float* __restrict__ bq,
    const float* __restrict__ gk, const float* __restrict__ bk)
{
    extern __shared__ __align__(16) uint32_t sm[];
    uint32_t* sPh = sm + AT_PH;
    uint32_t* sKv = sm + AT_KV;
    float*    pmax = (float*)(sm + AT_PMAX);
    float*    psum = (float*)(sm + AT_PSUM);

    const int tid  = threadIdx.x;
    const int wid  = tid >> 5;
    const int lane = tid & 31;

    const int bb  = blockIdx.x >> 8;
    const int wnd = blockIdx.x & 255;
    const int base_px = ((wnd >> 4) << 3) * 128 + ((wnd & 15) << 3);
    const int wbase = wnd * 64;

    const __half* qb = g_qraw + (size_t)bb * IMG;
    const __half* kb = g_kraw + (size_t)bb * IMG;

    const int wm = wid & 3;
    const int wn = wid >> 2;

    const int p_  = tid >> 4;
    const int pg  = (tid & 15) * 4;

    float acc[4][4];
#pragma unroll
    for (int i = 0; i < 4; i++)
#pragma unroll
        for (int j = 0; j < 4; j++) acc[i][j] = 0.f;

    uint2 q0h, q1h, k0h, k1h;
    {
        const size_t ga0 = (size_t)(2 * p_) * HW + wbase + pg;
        q0h = *(const uint2*)(qb + ga0);
        q1h = *(const uint2*)(qb + ga0 + HW);
        k0h = *(const uint2*)(kb + ga0);
        k1h = *(const uint2*)(kb + ga0 + HW);
    }

    // ================= Phase S (ping-pong staging, 1 barrier/chunk) =======
#pragma unroll 1
    for (int cc = 0; cc < 8; cc++) {
        uint32_t* sQb = sm + (cc & 1) * 2304;      // this chunk's Q buffer
        uint32_t* sKb = sQb + 1152;                // this chunk's K buffer

        const int c0 = cc * 32 + 2 * p_;
        const int g  = c0 >> 3;
        float4 q0 = h4_to_f4(q0h), q1 = h4_to_f4(q1h);
        float4 k0 = h4_to_f4(k0h), k1 = h4_to_f4(k1h);
        uint4 tq, tk;
        uint2 kv0, kv1;
        {
            float rq_ = g_rstd[bb * 32 + g], mq_ = g_mean[bb * 32 + g];
            float a0 = rq_ * gq[c0],     d0 = fmaf(-mq_, a0, bq[c0]);
            float a1 = rq_ * gq[c0 + 1], d1 = fmaf(-mq_, a1, bq[c0 + 1]);
            tq.x = pack_h2(fmaf(q0.x, a0, d0), fmaf(q1.x, a1, d1));
            tq.y = pack_h2(fmaf(q0.y, a0, d0), fmaf(q1.y, a1, d1));
            tq.z = pack_h2(fmaf(q0.z, a0, d0), fmaf(q1.z, a1, d1));
            tq.w = pack_h2(fmaf(q0.w, a0, d0), fmaf(q1.w, a1, d1));
        }
        {
            float rk_ = g_rstd[256 + bb * 32 + g], mk_ = g_mean[256 + bb * 32 + g];
            float a0 = rk_ * gk[c0],     d0 = fmaf(-mk_, a0, bk[c0]);
            float a1 = rk_ * gk[c0 + 1], d1 = fmaf(-mk_, a1, bk[c0 + 1]);
            float f00 = fmaf(k0.x, a0, d0), f01 = fmaf(k0.y, a0, d0);
            float f02 = fmaf(k0.z, a0, d0), f03 = fmaf(k0.w, a0, d0);
            float f10 = fmaf(k1.x, a1, d1), f11 = fmaf(k1.y, a1, d1);
            float f12 = fmaf(k1.z, a1, d1), f13 = fmaf(k1.w, a1, d1);
            tk.x = pack_h2(f00, f10);
            tk.y = pack_h2(f01, f11);
            tk.z = pack_h2(f02, f12);
            tk.w = pack_h2(f03, f13);
            kv0 = make_uint2(pack_h2(f00, f01), pack_h2(f02, f03));
            kv1 = make_uint2(pack_h2(f10, f11), pack_h2(f12, f13));
        }

        if (cc < 7) {
            const size_t gan = (size_t)((cc + 1) * 32 + 2 * p_) * HW + wbase + pg;
            q0h = *(const uint2*)(qb + gan);
            q1h = *(const uint2*)(qb + gan + HW);
            k0h = *(const uint2*)(kb + gan);
            k1h = *(const uint2*)(kb + gan + HW);
        }

        // write into this chunk's buffer; the barrier below both publishes
        // these writes and (for cc>=2) guarantees chunk cc-2's mma reads of
        // this same region finished (they precede the cc-1 barrier).
        *(uint4*)&sQb[p_ * QP_ST + pg] = tq;
        *(uint4*)&sKb[p_ * QP_ST + pg] = tk;
        *(uint2*)&sKv[(size_t)c0 * KV_ST + (pg >> 1)]       = kv0;
        *(uint2*)&sKv[(size_t)(c0 + 1) * KV_ST + (pg >> 1)] = kv1;
        __syncthreads();

#pragma unroll
        for (int ks = 0; ks < 2; ks++) {
            const int kp = ks * 8 + (lane & 3);
            const int mrow = wm * 16 + (lane >> 2);
            uint32_t a[4];
            a[0] = sQb[kp * QP_ST + mrow];
            a[1] = sQb[kp * QP_ST + mrow + 8];
            a[2] = sQb[(kp + 4) * QP_ST + mrow];
            a[3] = sQb[(kp + 4) * QP_ST + mrow + 8];
#pragma unroll
            for (int nb = 0; nb < 4; nb++) {
                const int ncol = wn * 32 + nb * 8 + (lane >> 2);
                uint32_t b0 = sKb[kp * QP_ST + ncol];
                uint32_t b1 = sKb[(kp + 4) * QP_ST + ncol];
                mmaf16(acc[nb], a, b0, b1);
            }
        }
    }

    // ================= register softmax =================
    const int rA = wm * 16 + (lane >> 2);
    const int rB = rA + 8;
    {
#pragma unroll
        for (int nb = 0; nb < 4; nb++)
#pragma unroll
            for (int r = 0; r < 4; r++) acc[nb][r] *= 0.0625f;

        float mA = acc[0][0], mB = acc[0][2];
#pragma unroll
        for (int nb = 0; nb < 4; nb++) {
            mA = fmaxf(mA, fmaxf(acc[nb][0], acc[nb][1]));
            mB = fmaxf(mB, fmaxf(acc[nb][2], acc[nb][3]));
        }
        mA = fmaxf(mA, __shfl_xor_sync(0xffffffffu, mA, 1));
        mA = fmaxf(mA, __shfl_xor_sync(0xffffffffu, mA, 2));
        mB = fmaxf(mB, __shfl_xor_sync(0xffffffffu, mB, 1));
        mB = fmaxf(mB, __shfl_xor_sync(0xffffffffu, mB, 2));
        __syncthreads();   // all mma(7) reads done; pmax/psum safe to write
        if ((lane & 3) == 0) {
            pmax[rA * 2 + wn] = mA;
            pmax[rB * 2 + wn] = mB;
        }
        __syncthreads();

        float MA = fmaxf(pmax[rA * 2], pmax[rA * 2 + 1]);
        float MB = fmaxf(pmax[rB * 2], pmax[rB * 2 + 1]);
        float sA = 0.f, sB = 0.f;
#pragma unroll
        for (int nb = 0; nb < 4; nb++) {
            acc[nb][0] = __expf(acc[nb][0] - MA);
            acc[nb][1] = __expf(acc[nb][1] - MA);
            acc[nb][2] = __expf(acc[nb][2] - MB);
            acc[nb][3] = __expf(acc[nb][3] - MB);
            sA += acc[nb][0] + acc[nb][1];
            sB += acc[nb][2] + acc[nb][3];
        }
        sA += __shfl_xor_sync(0xffffffffu, sA, 1);
        sA += __shfl_xor_sync(0xffffffffu, sA, 2);
        sB += __shfl_xor_sync(0xffffffffu, sB, 1);
        sB += __shfl_xor_sync(0xffffffffu, sB, 2);
        if ((lane & 3) == 0) {
            psum[rA * 2 + wn] = sA;
            psum[rB * 2 + wn] = sB;
        }
        __syncthreads();

        float invA = 1.f / (psum[rA * 2] + psum[rA * 2 + 1]);
        float invB = 1.f / (psum[rB * 2] + psum[rB * 2 + 1]);
#pragma unroll
        for (int nb = 0; nb < 4; nb++) {
            int pcol = wn * 16 + nb * 4 + (lane & 3);
            sPh[rA * PH_ST + pcol] = pack_h2(acc[nb][0] * invA, acc[nb][1] * invA);
            sPh[rB * PH_ST + pcol] = pack_h2(acc[nb][2] * invB, acc[nb][3] * invB);
        }
    }
    __syncthreads();   // sPh published; buffer0 region free for sO

    // ================= Phase PV (identical to R10) =================
    float* sO = (float*)sm;   // [32 ch][SP_ST px] in buffer0 region

    const int xc0 = tid >> 4;
    const int xr0 = tid & 15;
    const int xc1 = 16 + xc0;
    float4 xA, xB;
    {
        size_t ga = (size_t)bb * IMG + base_px +
                    (size_t)(xr0 >> 1) * 128 + (xr0 & 1) * 4;
        xA = *(const float4*)(xlo + ga + (size_t)xc0 * HW);
        xB = *(const float4*)(xlo + ga + (size_t)xc1 * HW);
    }

#pragma unroll 1
    for (int cc = 0; cc < 8; cc++) {
        float acc2[2][4];
#pragma unroll
        for (int nb = 0; nb < 2; nb++)
#pragma unroll
            for (int r = 0; r < 4; r++) acc2[nb][r] = 0.f;

#pragma unroll
        for (int ks = 0; ks < 4; ks++) {
            const int jp = ks * 8 + (lane & 3);
            const int i0 = wm * 16 + (lane >> 2);
            uint32_t a[4];
            a[0] = sPh[i0 * PH_ST + jp];
            a[1] = sPh[(i0 + 8) * PH_ST + jp];
            a[2] = sPh[i0 * PH_ST + jp + 4];
            a[3] = sPh[(i0 + 8) * PH_ST + jp + 4];
#pragma unroll
            for (int nb = 0; nb < 2; nb++) {
                const int c = cc * 32 + wn * 16 + nb * 8 + (lane >> 2);
                uint32_t b0 = sKv[c * KV_ST + jp];
                uint32_t b1 = sKv[c * KV_ST + jp + 4];
                mmaf16(acc2[nb], a, b0, b1);
            }
        }

        __syncthreads();

        {
            const int px = wm * 16 + (lane >> 2);
#pragma unroll
            for (int nb = 0; nb < 2; nb++) {
                const int chl = wn * 16 + nb * 8 + (lane & 3) * 2;
                sO[chl * SP_ST + px]           = acc2[nb][0];
                sO[(chl + 1) * SP_ST + px]     = acc2[nb][1];
                sO[chl * SP_ST + px + 8]       = acc2[nb][2];
                sO[(chl + 1) * SP_ST + px + 8] = acc2[nb][3];
            }
        }
        __syncthreads();

        {
            size_t gbase = (size_t)bb * IMG + base_px +
                           (size_t)(xr0 >> 1) * 128 + (xr0 & 1) * 4;
            int so_off = (xr0 >> 1) * 8 + (xr0 & 1) * 4;
            float4 o0 = *(const float4*)&sO[xc0 * SP_ST + so_off];
            float4 o1 = *(const float4*)&sO[xc1 * SP_ST + so_off];
            o0.x += xA.x; o0.y += xA.y; o0.z += xA.z; o0.w += xA.w;
            o1.x += xB.x; o1.y += xB.y; o1.z += xB.z; o1.w += xB.w;
            *(float4*)(outp + gbase + (size_t)(cc * 32 + xc0) * HW) = o0;
            *(float4*)(outp + gbase + (size_t)(cc * 32 + xc1) * HW) = o1;
            if (cc < 7) {
                xA = *(const float4*)(xlo + gbase + (size_t)((cc + 1) * 32 + xc0) * HW);
                xB = *(const float4*)(xlo + gbase + (size_t)((cc + 1) * 32 + xc1) * HW);
            }
        }
    }
}

// ---------------------------------------------------------------------------
// Launcher
// ---------------------------------------------------------------------------
extern "C" void kernel_launch(void* const* d_in, const int* in_sizes, int n_in,
                              void* d_out, int out_size)
{
    const float* x_low  = (const float*)d_in[0];
    const float* x_high = (const float*)d_in[1];
    const float* wq     = (const float*)d_in[2];
    const float* wk     = (const float*)d_in[3];
    const float* gq     = (const float*)d_in[4];
    const float* bq     = (const float*)d_in[5];
    const float* gk     = (const float*)d_in[6];
    const float* bk     = (const float*)d_in[7];
    float* outp = (float*)d_out;

    prep_afrag<<<256, 256>>>(wq, wk);

    proj_mma<<<dim3(2, 1024, 2), 256>>>(x_low, x_high);

    stats_finalize<<<512, 128>>>();

    cudaFuncSetAttribute(attn_mma,
                         cudaFuncAttributeMaxDynamicSharedMemorySize,
                         AT_SMEM_BYTES);
    attn_mma<<<2048, 256, AT_SMEM_BYTES>>>(x_low, outp, gq, bq, gk, bk);
}

// round 13
// speedup vs baseline: 1.1279x; 1.0329x over previous
#include <cuda_runtime.h>
#include <cuda_fp16.h>
#include <cstdint>

// ---------------------------------------------------------------------------
// Problem constants
// ---------------------------------------------------------------------------
#define BATCH   8
#define CH      256
#define HW      16384
#define IMG     (CH * HW)
#define GROUPS  32
#define GSZ     (CH / GROUPS)
#define NPIX    64
#define EPS     1e-5f

// g_qraw/g_kraw: fp16, WINDOW-TILED pixel layout within each channel:
//   px' = window_id * 64 + (y&7)*8 + (x&7),  window_id = (y>>3)*16 + (x>>3)
static __device__ __half g_qraw[(size_t)BATCH * IMG];
static __device__ __half g_kraw[(size_t)BATCH * IMG];
static __device__ float g_mean[2 * BATCH * GROUPS];
static __device__ float g_rstd[2 * BATCH * GROUPS];
// Pre-permuted fp16 A fragments (half2 k-pairs, m16n8k16 layout)
static __device__ uint32_t g_afragh[65536];
// per-(tensor,batch,group) x per-pixel-tile partial (sum, sumsq)
static __device__ float g_psum[512 * 256];

// ---------------------------------------------------------------------------
// helpers
// ---------------------------------------------------------------------------
__device__ __forceinline__ uint32_t pack_h2(float x, float y) {
    __half2 h = __float22half2_rn(make_float2(x, y));
    return *(uint32_t*)&h;
}
__device__ __forceinline__ float4 h4_to_f4(uint2 v) {
    float2 a = __half22float2(*(__half2*)&v.x);
    float2 b = __half22float2(*(__half2*)&v.y);
    return make_float4(a.x, a.y, b.x, b.y);
}

__device__ __forceinline__ void mmaf16(float d[4], const uint32_t a[4],
                                       uint32_t b0, uint32_t b1) {
    asm volatile(
        "mma.sync.aligned.m16n8k16.row.col.f32.f16.f16.f32 "
        "{%0,%1,%2,%3}, {%4,%5,%6,%7}, {%8,%9}, {%0,%1,%2,%3};"
        : "+f"(d[0]), "+f"(d[1]), "+f"(d[2]), "+f"(d[3])
        : "r"(a[0]), "r"(a[1]), "r"(a[2]), "r"(a[3]), "r"(b0), "r"(b1));
}

__device__ __forceinline__ uint32_t smem_u32(const void* p) {
    uint32_t a;
    asm("{ .reg .u64 t; cvta.to.shared.u64 t, %1; cvt.u32.u64 %0, t; }"
        : "=r"(a) : "l"(p));
    return a;
}

__device__ __forceinline__ void cpa16(uint32_t dst, const void* src) {
    asm volatile("cp.async.cg.shared.global [%0], [%1], 16;"
                 :: "r"(dst), "l"(src));
}
#define CPA_COMMIT() asm volatile("cp.async.commit_group;" ::: "memory")
#define CPA_WAIT(N)  asm volatile("cp.async.wait_group %0;" :: "n"(N) : "memory")

// ---------------------------------------------------------------------------
// Kernel 0: build fragment-ordered fp16 A operand (half2 k-pairs).
// ---------------------------------------------------------------------------
__global__ void __launch_bounds__(256) prep_afrag(
    const float* __restrict__ wq, const float* __restrict__ wk)
{
    int idx = blockIdx.x * 256 + threadIdx.x;   // 0..65535
    int reg   = idx & 3;
    int lane  = (idx >> 2) & 31;
    int ks    = (idx >> 7) & 1;
    int mbg   = (idx >> 8) & 7;
    int chunk = (idx >> 11) & 7;
    int mt    = (idx >> 14) & 1;
    int t     = (idx >> 15) & 1;

    int m  = mt * 128 + mbg * 16 + (reg & 1) * 8 + (lane >> 2);
    int kp = (lane & 3) + ((reg >> 1) & 1) * 4;
    int k  = chunk * 32 + ks * 16 + kp * 2;
    const float* W = t ? wk : wq;
    g_afragh[idx] = pack_h2(W[m * CH + k], W[m * CH + k + 1]);
}

// ---------------------------------------------------------------------------
// Kernel 1: projection GEMM via fp16 m16n8k16 + fused GroupNorm partials.
// R13: A cp.async for chunk c+1 issued immediately after the top-of-loop
// barrier (destination buffer's readers finished before that barrier), so
// the L2 latency overlaps the whole MMA + B-staging window.
// ---------------------------------------------------------------------------
#define BH_ST 136

__global__ void __launch_bounds__(256, 2) proj_mma(
    const float* __restrict__ xlo, const float* __restrict__ xhi)
{
    __shared__ uint32_t sA[4096];     // A0 @0, A1 @2048
    __shared__ uint32_t sB[4352];     // B0 @0, B1 @2176
    const uint32_t aBase = smem_u32(sA);

    const int tid  = threadIdx.x;
    const int wid  = tid >> 5;
    const int lane = tid & 31;

    const int mt = blockIdx.x;
    const int tz = blockIdx.z;
    const float* X = tz ? xhi : xlo;
    __half*      Y = tz ? g_kraw : g_qraw;

    const int bb = blockIdx.y >> 7;
    const int yrow = blockIdx.y & 127;
    const int p0 = yrow << 7;
    const int m0 = mt << 7;

    const float* Xb = X + (size_t)bb * IMG + p0;
    const uint32_t* Agh = g_afragh + (size_t)(tz * 2 + mt) * 16384;

    const int wm = wid >> 2;
    const int wn = wid & 3;

    const int kp = tid >> 4;          // 0..15
    const int nq = (tid & 15) * 8;    // 0..120

    float acc[4][4][4];
#pragma unroll
    for (int i = 0; i < 4; i++)
#pragma unroll
        for (int j = 0; j < 4; j++)
#pragma unroll
            for (int r = 0; r < 4; r++) acc[i][j][r] = 0.f;

    float4 b00, b01, b10, b11;
    {
        const float* r0 = Xb + (size_t)(2 * kp) * HW + nq;
        b00 = *(const float4*)(r0);
        b01 = *(const float4*)(r0 + 4);
        b10 = *(const float4*)(r0 + HW);
        b11 = *(const float4*)(r0 + HW + 4);
    }
    {
        uint4 t0, t1;
        t0.x = pack_h2(b00.x, b10.x); t0.y = pack_h2(b00.y, b10.y);
        t0.z = pack_h2(b00.z, b10.z); t0.w = pack_h2(b00.w, b10.w);
        t1.x = pack_h2(b01.x, b11.x); t1.y = pack_h2(b01.y, b11.y);
        t1.z = pack_h2(b01.z, b11.z); t1.w = pack_h2(b01.w, b11.w);
        *(uint4*)&sB[kp * BH_ST + nq]     = t0;
        *(uint4*)&sB[kp * BH_ST + nq + 4] = t1;
    }
#pragma unroll
    for (int i = 0; i < 2; i++) {
        int idx = i * 256 + tid;
        cpa16(aBase + idx * 16, Agh + idx * 4);
    }
    CPA_COMMIT();

#pragma unroll 1
    for (int c = 0; c < 8; c++) {
        const int buf = c & 1;
        CPA_WAIT(0);
        __syncthreads();

        // EARLY issue of next chunk's A fragments (overlaps with all compute
        // below). Safe: buf^1's last readers were chunk c-1's MMAs, which
        // completed before the barrier above.
        if (c < 7) {
            const int nb_ = buf ^ 1;
#pragma unroll
            for (int i = 0; i < 2; i++) {
                int idx = i * 256 + tid;
                cpa16(aBase + (nb_ * 2048 + idx * 4) * 4,
                      Agh + (c + 1) * 2048 + idx * 4);
            }
            CPA_COMMIT();
            // B raw prefetch (registers, overlaps compute)
            const float* r0 = Xb + (size_t)((c + 1) * 32 + 2 * kp) * HW + nq;
            b00 = *(const float4*)(r0);
            b01 = *(const float4*)(r0 + 4);
            b10 = *(const float4*)(r0 + HW);
            b11 = *(const float4*)(r0 + HW + 4);
        }

        const uint32_t* Ab = sA + buf * 2048;
        const uint32_t* Bb = sB + buf * 2176;

#pragma unroll
        for (int ks = 0; ks < 2; ks++) {
            uint32_t afr[4][4];
#pragma unroll
            for (int mb = 0; mb < 4; mb++) {
                int mbg = wm * 4 + mb;
                *(uint4*)afr[mb] =
                    *(const uint4*)&Ab[(mbg * 2 + ks) * 128 + lane * 4];
            }
            const int krow = ks * 8 + (lane & 3);
            const int ncol = wn * 32 + (lane >> 2);
#pragma unroll
            for (int nb = 0; nb < 4; nb++) {
                uint32_t b0 = Bb[krow * BH_ST + ncol + nb * 8];
                uint32_t b1 = Bb[(krow + 4) * BH_ST + ncol + nb * 8];
#pragma unroll
                for (int mb = 0; mb < 4; mb++)
                    mmaf16(acc[mb][nb], afr[mb], b0, b1);
            }
        }

        // stage next B chunk into the other buffer (after compute; same
        // safety argument as the cp.async above)
        if (c < 7) {
            const int nb_ = buf ^ 1;
            uint4 t0, t1;
            t0.x = pack_h2(b00.x, b10.x); t0.y = pack_h2(b00.y, b10.y);
            t0.z = pack_h2(b00.z, b10.z); t0.w = pack_h2(b00.w, b10.w);
            t1.x = pack_h2(b01.x, b11.x); t1.y = pack_h2(b01.y, b11.y);
            t1.z = pack_h2(b01.z, b11.z); t1.w = pack_h2(b01.w, b11.w);
            *(uint4*)&sB[nb_ * 2176 + kp * BH_ST + nq]     = t0;
            *(uint4*)&sB[nb_ * 2176 + kp * BH_ST + nq + 4] = t1;
        }
    }

    // ---- fused GroupNorm partial statistics ----
    __shared__ float red[16][4][2];
#pragma unroll
    for (int mb = 0; mb < 4; mb++) {
        float sE = 0.f, qE = 0.f, sO_ = 0.f, qO = 0.f;
#pragma unroll
        for (int nb = 0; nb < 4; nb++) {
            sE += acc[mb][nb][0] + acc[mb][nb][1];
            qE += acc[mb][nb][0] * acc[mb][nb][0] + acc[mb][nb][1] * acc[mb][nb][1];
            sO_ += acc[mb][nb][2] + acc[mb][nb][3];
            qO += acc[mb][nb][2] * acc[mb][nb][2] + acc[mb][nb][3] * acc[mb][nb][3];
        }
#pragma unroll
        for (int off = 16; off; off >>= 1) {
            sE += __shfl_xor_sync(0xffffffffu, sE, off);
            qE += __shfl_xor_sync(0xffffffffu, qE, off);
            sO_ += __shfl_xor_sync(0xffffffffu, sO_, off);
            qO += __shfl_xor_sync(0xffffffffu, qO, off);
        }
        if (lane == 0) {
            int gl = wm * 8 + mb * 2;
            red[gl][wn][0] = sE;     red[gl][wn][1] = qE;
            red[gl + 1][wn][0] = sO_; red[gl + 1][wn][1] = qO;
        }
    }
    __syncthreads();
    if (tid < 32) {
        int gl = tid >> 1, sq = tid & 1;
        float v = red[gl][0][sq] + red[gl][1][sq] + red[gl][2][sq] + red[gl][3][sq];
        g_psum[((size_t)((tz * 8 + bb) * 32) + mt * 16 + gl) * 256 + yrow * 2 + sq] = v;
    }

    // ---- epilogue: fp16 window-tiled store ----
    const int base2 = (yrow >> 3) * 1024 + (yrow & 7) * 8;
    __half* Yb = Y + (size_t)bb * IMG + base2;
    const int rl = lane >> 2;
    const int cl = (lane & 3) * 2;
#pragma unroll
    for (int mb = 0; mb < 4; mb++) {
        int mrow = m0 + wm * 64 + mb * 16 + rl;
#pragma unroll
        for (int nb = 0; nb < 4; nb++) {
            int noff = (wn * 4 + nb) * 64 + cl;
            __half2 v0 = __floats2half2_rn(acc[mb][nb][0], acc[mb][nb][1]);
            __half2 v1 = __floats2half2_rn(acc[mb][nb][2], acc[mb][nb][3]);
            *(__half2*)(Yb + (size_t)mrow * HW + noff)       = v0;
            *(__half2*)(Yb + (size_t)(mrow + 8) * HW + noff) = v1;
        }
    }
}

// ---------------------------------------------------------------------------
// Kernel 2: GroupNorm stats finalize.
// ---------------------------------------------------------------------------
__global__ void __launch_bounds__(128) stats_finalize()
{
    const int id  = blockIdx.x;
    const int tid = threadIdx.x;
    const float* p = g_psum + (size_t)id * 256;

    __shared__ float rs[128], rq[128];
    rs[tid] = p[tid * 2];
    rq[tid] = p[tid * 2 + 1];
    __syncthreads();
    for (int o = 64; o; o >>= 1) {
        if (tid < o) { rs[tid] += rs[tid + o]; rq[tid] += rq[tid + o]; }
        __syncthreads();
    }
    if (tid == 0) {
        const float invN = 1.f / (float)(GSZ * HW);
        float m   = rs[0] * invN;
        float var = rq[0] * invN - m * m;
        g_mean[id] = m;
        g_rstd[id] = rsqrtf(var + EPS);
    }
}

// ---------------------------------------------------------------------------
// Kernel 3: windowed attention (identical to R12).
// ---------------------------------------------------------------------------
#define QP_ST 72
#define SP_ST 68
#define PH_ST 36
#define KV_ST 36
#define AT_PH   2304
#define AT_KV   4608
#define AT_PMAX 13824
#define AT_PSUM 13952
#define AT_SMEM_BYTES (14080 * 4)

__global__ void __launch_bounds__(256) attn_mma(
    const float* __restrict__ xlo, float* __restrict__ outp,
    const float* __restrict__ gq, const float* __restrict__ bq,
    const float* __restrict__ gk, const float* __restrict__ bk)
{
    extern __shared__ __align__(16) uint32_t sm[];
    uint32_t* sPh = sm + AT_PH;
    uint32_t* sKv = sm + AT_KV;
    float*    pmax = (float*)(sm + AT_PMAX);
    float*    psum = (float*)(sm + AT_PSUM);

    const int tid  = threadIdx.x;
    const int wid  = tid >> 5;
    const int lane = tid & 31;

    const int bb  = blockIdx.x >> 8;
    const int wnd = blockIdx.x & 255;
    const int base_px = ((wnd >> 4) << 3) * 128 + ((wnd & 15) << 3);
    const int wbase = wnd * 64;

    const __half* qb = g_qraw + (size_t)bb * IMG;
    const __half* kb = g_kraw + (size_t)bb * IMG;

    const int wm = wid & 3;
    const int wn = wid >> 2;

    const int p_  = tid >> 4;
    const int pg  = (tid & 15) * 4;

    float acc[4][4];
#pragma unroll
    for (int i = 0; i < 4; i++)
#pragma unroll
        for (int j = 0; j < 4; j++) acc[i][j] = 0.f;

    uint2 q0h, q1h, k0h, k1h;
    {
        const size_t ga0 = (size_t)(2 * p_) * HW + wbase + pg;
        q0h = *(const uint2*)(qb + ga0);
        q1h = *(const uint2*)(qb + ga0 + HW);
        k0h = *(const uint2*)(kb + ga0);
        k1h = *(const uint2*)(kb + ga0 + HW);
    }

    // ================= Phase S (ping-pong staging, 1 barrier/chunk) =======
#pragma unroll 1
    for (int cc = 0; cc < 8; cc++) {
        uint32_t* sQb = sm + (cc & 1) * 2304;
        uint32_t* sKb = sQb + 1152;

        const int c0 = cc * 32 + 2 * p_;
        const int g  = c0 >> 3;
        float4 q0 = h4_to_f4(q0h), q1 = h4_to_f4(q1h);
        float4 k0 = h4_to_f4(k0h), k1 = h4_to_f4(k1h);
        uint4 tq, tk;
        uint2 kv0, kv1;
        {
            float rq_ = g_rstd[bb * 32 + g], mq_ = g_mean[bb * 32 + g];
            float a0 = rq_ * gq[c0],     d0 = fmaf(-mq_, a0, bq[c0]);
            float a1 = rq_ * gq[c0 + 1], d1 = fmaf(-mq_, a1, bq[c0 + 1]);
            tq.x = pack_h2(fmaf(q0.x, a0, d0), fmaf(q1.x, a1, d1));
            tq.y = pack_h2(fmaf(q0.y, a0, d0), fmaf(q1.y, a1, d1));
            tq.z = pack_h2(fmaf(q0.z, a0, d0), fmaf(q1.z, a1, d1));
            tq.w = pack_h2(fmaf(q0.w, a0, d0), fmaf(q1.w, a1, d1));
        }
        {
            float rk_ = g_rstd[256 + bb * 32 + g], mk_ = g_mean[256 + bb * 32 + g];
            float a0 = rk_ * gk[c0],     d0 = fmaf(-mk_, a0, bk[c0]);
            float a1 = rk_ * gk[c0 + 1], d1 = fmaf(-mk_, a1, bk[c0 + 1]);
            float f00 = fmaf(k0.x, a0, d0), f01 = fmaf(k0.y, a0, d0);
            float f02 = fmaf(k0.z, a0, d0), f03 = fmaf(k0.w, a0, d0);
            float f10 = fmaf(k1.x, a1, d1), f11 = fmaf(k1.y, a1, d1);
            float f12 = fmaf(k1.z, a1, d1), f13 = fmaf(k1.w, a1, d1);
            tk.x = pack_h2(f00, f10);
            tk.y = pack_h2(f01, f11);
            tk.z = pack_h2(f02, f12);
            tk.w = pack_h2(f03, f13);
            kv0 = make_uint2(pack_h2(f00, f01), pack_h2(f02, f03));
            kv1 = make_uint2(pack_h2(f10, f11), pack_h2(f12, f13));
        }

        if (cc < 7) {
            const size_t gan = (size_t)((cc + 1) * 32 + 2 * p_) * HW + wbase + pg;
            q0h = *(const uint2*)(qb + gan);
            q1h = *(const uint2*)(qb + gan + HW);
            k0h = *(const uint2*)(kb + gan);
            k1h = *(const uint2*)(kb + gan + HW);
        }

        *(uint4*)&sQb[p_ * QP_ST + pg] = tq;
        *(uint4*)&sKb[p_ * QP_ST + pg] = tk;
        *(uint2*)&sKv[(size_t)c0 * KV_ST + (pg >> 1)]       = kv0;
        *(uint2*)&sKv[(size_t)(c0 + 1) * KV_ST + (pg >> 1)] = kv1;
        __syncthreads();

#pragma unroll
        for (int ks = 0; ks < 2; ks++) {
            const int kp = ks * 8 + (lane & 3);
            const int mrow = wm * 16 + (lane >> 2);
            uint32_t a[4];
            a[0] = sQb[kp * QP_ST + mrow];
            a[1] = sQb[kp * QP_ST + mrow + 8];
            a[2] = sQb[(kp + 4) * QP_ST + mrow];
            a[3] = sQb[(kp + 4) * QP_ST + mrow + 8];
#pragma unroll
            for (int nb = 0; nb < 4; nb++) {
                const int ncol = wn * 32 + nb * 8 + (lane >> 2);
                uint32_t b0 = sKb[kp * QP_ST + ncol];
                uint32_t b1 = sKb[(kp + 4) * QP_ST + ncol];
                mmaf16(acc[nb], a, b0, b1);
            }
        }
    }

    // ================= register softmax =================
    const int rA = wm * 16 + (lane >> 2);
    const int rB = rA + 8;
    {
#pragma unroll
        for (int nb = 0; nb < 4; nb++)
#pragma unroll
            for (int r = 0; r < 4; r++) acc[nb][r] *= 0.0625f;

        float mA = acc[0][0], mB = acc[0][2];
#pragma unroll
        for (int nb = 0; nb < 4; nb++) {
            mA = fmaxf(mA, fmaxf(acc[nb][0], acc[nb][1]));
            mB = fmaxf(mB, fmaxf(acc[nb][2], acc[nb][3]));
        }
        mA = fmaxf(mA, __shfl_xor_sync(0xffffffffu, mA, 1));
        mA = fmaxf(mA, __shfl_xor_sync(0xffffffffu, mA, 2));
        mB = fmaxf(mB, __shfl_xor_sync(0xffffffffu, mB, 1));
        mB = fmaxf(mB, __shfl_xor_sync(0xffffffffu, mB, 2));
        __syncthreads();
        if ((lane & 3) == 0) {
            pmax[rA * 2 + wn] = mA;
            pmax[rB * 2 + wn] = mB;
        }
        __syncthreads();

        float MA = fmaxf(pmax[rA * 2], pmax[rA * 2 + 1]);
        float MB = fmaxf(pmax[rB * 2], pmax[rB * 2 + 1]);
        float sA = 0.f, sB = 0.f;
#pragma unroll
        for (int nb = 0; nb < 4; nb++) {
            acc[nb][0] = __expf(acc[nb][0] - MA);
            acc[nb][1] = __expf(acc[nb][1] - MA);
            acc[nb][2] = __expf(acc[nb][2] - MB);
            acc[nb][3] = __expf(acc[nb][3] - MB);
            sA += acc[nb][0] + acc[nb][1];
            sB += acc[nb][2] + acc[nb][3];
        }
        sA += __shfl_xor_sync(0xffffffffu, sA, 1);
        sA += __shfl_xor_sync(0xffffffffu, sA, 2);
        sB += __shfl_xor_sync(0xffffffffu, sB, 1);
        sB += __shfl_xor_sync(0xffffffffu, sB, 2);
        if ((lane & 3) == 0) {
            psum[rA * 2 + wn] = sA;
            psum[rB * 2 + wn] = sB;
        }
        __syncthreads();

        float invA = 1.f / (psum[rA * 2] + psum[rA * 2 + 1]);
        float invB = 1.f / (psum[rB * 2] + psum[rB * 2 + 1]);
#pragma unroll
        for (int nb = 0; nb < 4; nb++) {
            int pcol = wn * 16 + nb * 4 + (lane & 3);
            sPh[rA * PH_ST + pcol] = pack_h2(acc[nb][0] * invA, acc[nb][1] * invA);
            sPh[rB * PH_ST + pcol] = pack_h2(acc[nb][2] * invB, acc[nb][3] * invB);
        }
    }
    __syncthreads();

    // ================= Phase PV =================
    float* sO = (float*)sm;

    const int xc0 = tid >> 4;
    const int xr0 = tid & 15;
    const int xc1 = 16 + xc0;
    float4 xA, xB;
    {
        size_t ga = (size_t)bb * IMG + base_px +
                    (size_t)(xr0 >> 1) * 128 + (xr0 & 1) * 4;
        xA = *(const float4*)(xlo + ga + (size_t)xc0 * HW);
        xB = *(const float4*)(xlo + ga + (size_t)xc1 * HW);
    }

#pragma unroll 1
    for (int cc = 0; cc < 8; cc++) {
        float acc2[2][4];
#pragma unroll
        for (int nb = 0; nb < 2; nb++)
#pragma unroll
            for (int r = 0; r < 4; r++) acc2[nb][r] = 0.f;

#pragma unroll
        for (int ks = 0; ks < 4; ks++) {
            const int jp = ks * 8 + (lane & 3);
            const int i0 = wm * 16 + (lane >> 2);
            uint32_t a[4];
            a[0] = sPh[i0 * PH_ST + jp];
            a[1] = sPh[(i0 + 8) * PH_ST + jp];
            a[2] = sPh[i0 * PH_ST + jp + 4];
            a[3] = sPh[(i0 + 8) * PH_ST + jp + 4];
#pragma unroll
            for (int nb = 0; nb < 2; nb++) {
                const int c = cc * 32 + wn * 16 + nb * 8 + (lane >> 2);
                uint32_t b0 = sKv[c * KV_ST + jp];
                uint32_t b1 = sKv[c * KV_ST + jp + 4];
                mmaf16(acc2[nb], a, b0, b1);
            }
        }

        __syncthreads();

        {
            const int px = wm * 16 + (lane >> 2);
#pragma unroll
            for (int nb = 0; nb < 2; nb++) {
                const int chl = wn * 16 + nb * 8 + (lane & 3) * 2;
                sO[chl * SP_ST + px]           = acc2[nb][0];
                sO[(chl + 1) * SP_ST + px]     = acc2[nb][1];
                sO[chl * SP_ST + px + 8]       = acc2[nb][2];
                sO[(chl + 1) * SP_ST + px + 8] = acc2[nb][3];
            }
        }
        __syncthreads();

        {
            size_t gbase = (size_t)bb * IMG + base_px +
                           (size_t)(xr0 >> 1) * 128 + (xr0 & 1) * 4;
            int so_off = (xr0 >> 1) * 8 + (xr0 & 1) * 4;
            float4 o0 = *(const float4*)&sO[xc0 * SP_ST + so_off];
            float4 o1 = *(const float4*)&sO[xc1 * SP_ST + so_off];
            o0.x += xA.x; o0.y += xA.y; o0.z += xA.z; o0.w += xA.w;
            o1.x += xB.x; o1.y += xB.y; o1.z += xB.z; o1.w += xB.w;
            *(float4*)(outp + gbase + (size_t)(cc * 32 + xc0) * HW) = o0;
            *(float4*)(outp + gbase + (size_t)(cc * 32 + xc1) * HW) = o1;
            if (cc < 7) {
                xA = *(const float4*)(xlo + gbase + (size_t)((cc + 1) * 32 + xc0) * HW);
                xB = *(const float4*)(xlo + gbase + (size_t)((cc + 1) * 32 + xc1) * HW);
            }
        }
    }
}

// ---------------------------------------------------------------------------
// Launcher
// ---------------------------------------------------------------------------
extern "C" void kernel_launch(void* const* d_in, const int* in_sizes, int n_in,
                              void* d_out, int out_size)
{
    const float* x_low  = (const float*)d_in[0];
    const float* x_high = (const float*)d_in[1];
    const float* wq     = (const float*)d_in[2];
    const float* wk     = (const float*)d_in[3];
    const float* gq     = (const float*)d_in[4];
    const float* bq     = (const float*)d_in[5];
    const float* gk     = (const float*)d_in[6];
    const float* bk     = (const float*)d_in[7];
    float* outp = (float*)d_out;

    prep_afrag<<<256, 256>>>(wq, wk);

    proj_mma<<<dim3(2, 1024, 2), 256>>>(x_low, x_high);

    stats_finalize<<<512, 128>>>();

    cudaFuncSetAttribute(attn_mma,
                         cudaFuncAttributeMaxDynamicSharedMemorySize,
                         AT_SMEM_BYTES);
    attn_mma<<<2048, 256, AT_SMEM_BYTES>>>(x_low, outp, gq, bq, gk, bk);
}

// round 14
// speedup vs baseline: 1.1350x; 1.0064x over previous
#include <cuda_runtime.h>
#include <cuda_fp16.h>
#include <cstdint>

// ---------------------------------------------------------------------------
// Problem constants
// ---------------------------------------------------------------------------
#define BATCH   8
#define CH      256
#define HW      16384
#define IMG     (CH * HW)
#define GROUPS  32
#define GSZ     (CH / GROUPS)
#define NPIX    64
#define EPS     1e-5f

// g_qraw/g_kraw: fp16, WINDOW-TILED pixel layout within each channel:
//   px' = window_id * 64 + (y&7)*8 + (x&7),  window_id = (y>>3)*16 + (x>>3)
static __device__ __half g_qraw[(size_t)BATCH * IMG];
static __device__ __half g_kraw[(size_t)BATCH * IMG];
static __device__ float g_mean[2 * BATCH * GROUPS];
static __device__ float g_rstd[2 * BATCH * GROUPS];
// Pre-permuted fp16 A fragments (half2 k-pairs, m16n8k16 layout)
static __device__ uint32_t g_afragh[65536];
// per-(tensor,batch,group) x per-pixel-tile partial (sum, sumsq)
static __device__ float g_psum[512 * 256];

// ---------------------------------------------------------------------------
// helpers
// ---------------------------------------------------------------------------
__device__ __forceinline__ uint32_t pack_h2(float x, float y) {
    __half2 h = __float22half2_rn(make_float2(x, y));
    return *(uint32_t*)&h;
}
__device__ __forceinline__ float4 h4_to_f4(uint2 v) {
    float2 a = __half22float2(*(__half2*)&v.x);
    float2 b = __half22float2(*(__half2*)&v.y);
    return make_float4(a.x, a.y, b.x, b.y);
}

__device__ __forceinline__ void mmaf16(float d[4], const uint32_t a[4],
                                       uint32_t b0, uint32_t b1) {
    asm volatile(
        "mma.sync.aligned.m16n8k16.row.col.f32.f16.f16.f32 "
        "{%0,%1,%2,%3}, {%4,%5,%6,%7}, {%8,%9}, {%0,%1,%2,%3};"
        : "+f"(d[0]), "+f"(d[1]), "+f"(d[2]), "+f"(d[3])
        : "r"(a[0]), "r"(a[1]), "r"(a[2]), "r"(a[3]), "r"(b0), "r"(b1));
}

__device__ __forceinline__ uint32_t smem_u32(const void* p) {
    uint32_t a;
    asm("{ .reg .u64 t; cvta.to.shared.u64 t, %1; cvt.u32.u64 %0, t; }"
        : "=r"(a) : "l"(p));
    return a;
}

__device__ __forceinline__ void cpa16(uint32_t dst, const void* src) {
    asm volatile("cp.async.cg.shared.global [%0], [%1], 16;"
                 :: "r"(dst), "l"(src));
}
#define CPA_COMMIT() asm volatile("cp.async.commit_group;" ::: "memory")
#define CPA_WAIT(N)  asm volatile("cp.async.wait_group %0;" :: "n"(N) : "memory")

// ---------------------------------------------------------------------------
// Kernel 0: build fragment-ordered fp16 A operand (half2 k-pairs).
// ---------------------------------------------------------------------------
__global__ void __launch_bounds__(256) prep_afrag(
    const float* __restrict__ wq, const float* __restrict__ wk)
{
    int idx = blockIdx.x * 256 + threadIdx.x;   // 0..65535
    int reg   = idx & 3;
    int lane  = (idx >> 2) & 31;
    int ks    = (idx >> 7) & 1;
    int mbg   = (idx >> 8) & 7;
    int chunk = (idx >> 11) & 7;
    int mt    = (idx >> 14) & 1;
    int t     = (idx >> 15) & 1;

    int m  = mt * 128 + mbg * 16 + (reg & 1) * 8 + (lane >> 2);
    int kp = (lane & 3) + ((reg >> 1) & 1) * 4;
    int k  = chunk * 32 + ks * 16 + kp * 2;
    const float* W = t ? wk : wq;
    g_afragh[idx] = pack_h2(W[m * CH + k], W[m * CH + k + 1]);
}

// ---------------------------------------------------------------------------
// Kernel 1: projection GEMM via fp16 m16n8k16 + fused GroupNorm partials.
// R14: ALL 8 chunks of the A operand (64 KB, L2-resident across 1024 CTAs)
// are loaded into smem ONCE in the prologue. The main loop has no cp.async
// and no waits — only the B ping-pong barrier. Dynamic smem = 81 KB.
// ---------------------------------------------------------------------------
#define BH_ST 136
#define PJ_A      0            // 16384 words: A chunks 0..7, 2048 words each
#define PJ_B      16384        // 2 x 2176 words ping-pong
#define PJ_SMEM_BYTES ((16384 + 2 * 2176) * 4)   // 83,968 bytes

__global__ void __launch_bounds__(256, 2) proj_mma(
    const float* __restrict__ xlo, const float* __restrict__ xhi)
{
    extern __shared__ __align__(16) uint32_t smu[];
    uint32_t* sA = smu + PJ_A;
    uint32_t* sB = smu + PJ_B;
    const uint32_t sbase = smem_u32(smu);

    const int tid  = threadIdx.x;
    const int wid  = tid >> 5;
    const int lane = tid & 31;

    const int mt = blockIdx.x;
    const int tz = blockIdx.z;
    const float* X = tz ? xhi : xlo;
    __half*      Y = tz ? g_kraw : g_qraw;

    const int bb = blockIdx.y >> 7;
    const int yrow = blockIdx.y & 127;
    const int p0 = yrow << 7;
    const int m0 = mt << 7;

    const float* Xb = X + (size_t)bb * IMG + p0;
    const uint32_t* Agh = g_afragh + (size_t)(tz * 2 + mt) * 16384;

    const int wm = wid >> 2;
    const int wn = wid & 3;

    const int kp = tid >> 4;          // 0..15
    const int nq = (tid & 15) * 8;    // 0..120

    float acc[4][4][4];
#pragma unroll
    for (int i = 0; i < 4; i++)
#pragma unroll
        for (int j = 0; j < 4; j++)
#pragma unroll
            for (int r = 0; r < 4; r++) acc[i][j][r] = 0.f;

    // ---- prologue: ALL A chunks via cp.async (64 KB, L2-resident) ----
#pragma unroll
    for (int i = 0; i < 16; i++) {
        int idx = i * 256 + tid;          // 0..4095 (uint4 granules)
        cpa16(sbase + (PJ_A + idx * 4) * 4, Agh + idx * 4);
    }
    CPA_COMMIT();

    // ---- chunk 0 B: LDG + pack + STS ----
    float4 b00, b01, b10, b11;
    {
        const float* r0 = Xb + (size_t)(2 * kp) * HW + nq;
        b00 = *(const float4*)(r0);
        b01 = *(const float4*)(r0 + 4);
        b10 = *(const float4*)(r0 + HW);
        b11 = *(const float4*)(r0 + HW + 4);
    }
    {
        uint4 t0, t1;
        t0.x = pack_h2(b00.x, b10.x); t0.y = pack_h2(b00.y, b10.y);
        t0.z = pack_h2(b00.z, b10.z); t0.w = pack_h2(b00.w, b10.w);
        t1.x = pack_h2(b01.x, b11.x); t1.y = pack_h2(b01.y, b11.y);
        t1.z = pack_h2(b01.z, b11.z); t1.w = pack_h2(b01.w, b11.w);
        *(uint4*)&sB[kp * BH_ST + nq]     = t0;
        *(uint4*)&sB[kp * BH_ST + nq + 4] = t1;
    }
    CPA_WAIT(0);        // A fully resident from here on

#pragma unroll 1
    for (int c = 0; c < 8; c++) {
        const int buf = c & 1;
        __syncthreads();   // publishes B(buf) STS; protects B(buf^1) rewrite

        // B raw prefetch for next chunk (registers; overlaps compute)
        if (c < 7) {
            const float* r0 = Xb + (size_t)((c + 1) * 32 + 2 * kp) * HW + nq;
            b00 = *(const float4*)(r0);
            b01 = *(const float4*)(r0 + 4);
            b10 = *(const float4*)(r0 + HW);
            b11 = *(const float4*)(r0 + HW + 4);
        }

        const uint32_t* Ab = sA + c * 2048;        // chunk-resident A
        const uint32_t* Bb = sB + buf * 2176;

#pragma unroll
        for (int ks = 0; ks < 2; ks++) {
            uint32_t afr[4][4];
#pragma unroll
            for (int mb = 0; mb < 4; mb++) {
                int mbg = wm * 4 + mb;
                *(uint4*)afr[mb] =
                    *(const uint4*)&Ab[(mbg * 2 + ks) * 128 + lane * 4];
            }
            const int krow = ks * 8 + (lane & 3);
            const int ncol = wn * 32 + (lane >> 2);
#pragma unroll
            for (int nb = 0; nb < 4; nb++) {
                uint32_t b0 = Bb[krow * BH_ST + ncol + nb * 8];
                uint32_t b1 = Bb[(krow + 4) * BH_ST + ncol + nb * 8];
#pragma unroll
                for (int mb = 0; mb < 4; mb++)
                    mmaf16(acc[mb][nb], afr[mb], b0, b1);
            }
        }

        // stage next B chunk into the other buffer (published by next barrier)
        if (c < 7) {
            const int nb_ = buf ^ 1;
            uint4 t0, t1;
            t0.x = pack_h2(b00.x, b10.x); t0.y = pack_h2(b00.y, b10.y);
            t0.z = pack_h2(b00.z, b10.z); t0.w = pack_h2(b00.w, b10.w);
            t1.x = pack_h2(b01.x, b11.x); t1.y = pack_h2(b01.y, b11.y);
            t1.z = pack_h2(b01.z, b11.z); t1.w = pack_h2(b01.w, b11.w);
            *(uint4*)&sB[nb_ * 2176 + kp * BH_ST + nq]     = t0;
            *(uint4*)&sB[nb_ * 2176 + kp * BH_ST + nq + 4] = t1;
        }
    }

    // ---- fused GroupNorm partial statistics ----
    __shared__ float red[16][4][2];
#pragma unroll
    for (int mb = 0; mb < 4; mb++) {
        float sE = 0.f, qE = 0.f, sO_ = 0.f, qO = 0.f;
#pragma unroll
        for (int nb = 0; nb < 4; nb++) {
            sE += acc[mb][nb][0] + acc[mb][nb][1];
            qE += acc[mb][nb][0] * acc[mb][nb][0] + acc[mb][nb][1] * acc[mb][nb][1];
            sO_ += acc[mb][nb][2] + acc[mb][nb][3];
            qO += acc[mb][nb][2] * acc[mb][nb][2] + acc[mb][nb][3] * acc[mb][nb][3];
        }
#pragma unroll
        for (int off = 16; off; off >>= 1) {
            sE += __shfl_xor_sync(0xffffffffu, sE, off);
            qE += __shfl_xor_sync(0xffffffffu, qE, off);
            sO_ += __shfl_xor_sync(0xffffffffu, sO_, off);
            qO += __shfl_xor_sync(0xffffffffu, qO, off);
        }
        if (lane == 0) {
            int gl = wm * 8 + mb * 2;
            red[gl][wn][0] = sE;     red[gl][wn][1] = qE;
            red[gl + 1][wn][0] = sO_; red[gl + 1][wn][1] = qO;
        }
    }
    __syncthreads();
    if (tid < 32) {
        int gl = tid >> 1, sq = tid & 1;
        float v = red[gl][0][sq] + red[gl][1][sq] + red[gl][2][sq] + red[gl][3][sq];
        g_psum[((size_t)((tz * 8 + bb) * 32) + mt * 16 + gl) * 256 + yrow * 2 + sq] = v;
    }

    // ---- epilogue: fp16 window-tiled store ----
    const int base2 = (yrow >> 3) * 1024 + (yrow & 7) * 8;
    __half* Yb = Y + (size_t)bb * IMG + base2;
    const int rl = lane >> 2;
    const int cl = (lane & 3) * 2;
#pragma unroll
    for (int mb = 0; mb < 4; mb++) {
        int mrow = m0 + wm * 64 + mb * 16 + rl;
#pragma unroll
        for (int nb = 0; nb < 4; nb++) {
            int noff = (wn * 4 + nb) * 64 + cl;
            __half2 v0 = __floats2half2_rn(acc[mb][nb][0], acc[mb][nb][1]);
            __half2 v1 = __floats2half2_rn(acc[mb][nb][2], acc[mb][nb][3]);
            *(__half2*)(Yb + (size_t)mrow * HW + noff)       = v0;
            *(__half2*)(Yb + (size_t)(mrow + 8) * HW + noff) = v1;
        }
    }
}

// ---------------------------------------------------------------------------
// Kernel 2: GroupNorm stats finalize.
// ---------------------------------------------------------------------------
__global__ void __launch_bounds__(128) stats_finalize()
{
    const int id  = blockIdx.x;
    const int tid = threadIdx.x;
    const float* p = g_psum + (size_t)id * 256;

    __shared__ float rs[128], rq[128];
    rs[tid] = p[tid * 2];
    rq[tid] = p[tid * 2 + 1];
    __syncthreads();
    for (int o = 64; o; o >>= 1) {
        if (tid < o) { rs[tid] += rs[tid + o]; rq[tid] += rq[tid + o]; }
        __syncthreads();
    }
    if (tid == 0) {
        const float invN = 1.f / (float)(GSZ * HW);
        float m   = rs[0] * invN;
        float var = rq[0] * invN - m * m;
        g_mean[id] = m;
        g_rstd[id] = rsqrtf(var + EPS);
    }
}

// ---------------------------------------------------------------------------
// Kernel 3: windowed attention (identical to R13).
// ---------------------------------------------------------------------------
#define QP_ST 72
#define SP_ST 68
#define PH_ST 36
#define KV_ST 36
#define AT_PH   2304
#define AT_KV   4608
#define AT_PMAX 13824
#define AT_PSUM 13952
#define AT_SMEM_BYTES (14080 * 4)

__global__ void __launch_bounds__(256) attn_mma(
    const float* __restrict__ xlo, float* __restrict__ outp,
    const float* __restrict__ gq, const float* __restrict__ bq,
    const float* __restrict__ gk, const float* __restrict__ bk)
{
    extern __shared__ __align__(16) uint32_t sm[];
    uint32_t* sPh = sm + AT_PH;
    uint32_t* sKv = sm + AT_KV;
    float*    pmax = (float*)(sm + AT_PMAX);
    float*    psum = (float*)(sm + AT_PSUM);

    const int tid  = threadIdx.x;
    const int wid  = tid >> 5;
    const int lane = tid & 31;

    const int bb  = blockIdx.x >> 8;
    const int wnd = blockIdx.x & 255;
    const int base_px = ((wnd >> 4) << 3) * 128 + ((wnd & 15) << 3);
    const int wbase = wnd * 64;

    const __half* qb = g_qraw + (size_t)bb * IMG;
    const __half* kb = g_kraw + (size_t)bb * IMG;

    const int wm = wid & 3;
    const int wn = wid >> 2;

    const int p_  = tid >> 4;
    const int pg  = (tid & 15) * 4;

    float acc[4][4];
#pragma unroll
    for (int i = 0; i < 4; i++)
#pragma unroll
        for (int j = 0; j < 4; j++) acc[i][j] = 0.f;

    uint2 q0h, q1h, k0h, k1h;
    {
        const size_t ga0 = (size_t)(2 * p_) * HW + wbase + pg;
        q0h = *(const uint2*)(qb + ga0);
        q1h = *(const uint2*)(qb + ga0 + HW);
        k0h = *(const uint2*)(kb + ga0);
        k1h = *(const uint2*)(kb + ga0 + HW);
    }

    // ================= Phase S (ping-pong staging, 1 barrier/chunk) =======
#pragma unroll 1
    for (int cc = 0; cc < 8; cc++) {
        uint32_t* sQb = sm + (cc & 1) * 2304;
        uint32_t* sKb = sQb + 1152;

        const int c0 = cc * 32 + 2 * p_;
        const int g  = c0 >> 3;
        float4 q0 = h4_to_f4(q0h), q1 = h4_to_f4(q1h);
        float4 k0 = h4_to_f4(k0h), k1 = h4_to_f4(k1h);
        uint4 tq, tk;
        uint2 kv0, kv1;
        {
            float rq_ = g_rstd[bb * 32 + g], mq_ = g_mean[bb * 32 + g];
            float a0 = rq_ * gq[c0],     d0 = fmaf(-mq_, a0, bq[c0]);
            float a1 = rq_ * gq[c0 + 1], d1 = fmaf(-mq_, a1, bq[c0 + 1]);
            tq.x = pack_h2(fmaf(q0.x, a0, d0), fmaf(q1.x, a1, d1));
            tq.y = pack_h2(fmaf(q0.y, a0, d0), fmaf(q1.y, a1, d1));
            tq.z = pack_h2(fmaf(q0.z, a0, d0), fmaf(q1.z, a1, d1));
            tq.w = pack_h2(fmaf(q0.w, a0, d0), fmaf(q1.w, a1, d1));
        }
        {
            float rk_ = g_rstd[256 + bb * 32 + g], mk_ = g_mean[256 + bb * 32 + g];
            float a0 = rk_ * gk[c0],     d0 = fmaf(-mk_, a0, bk[c0]);
            float a1 = rk_ * gk[c0 + 1], d1 = fmaf(-mk_, a1, bk[c0 + 1]);
            float f00 = fmaf(k0.x, a0, d0), f01 = fmaf(k0.y, a0, d0);
            float f02 = fmaf(k0.z, a0, d0), f03 = fmaf(k0.w, a0, d0);
            float f10 = fmaf(k1.x, a1, d1), f11 = fmaf(k1.y, a1, d1);
            float f12 = fmaf(k1.z, a1, d1), f13 = fmaf(k1.w, a1, d1);
            tk.x = pack_h2(f00, f10);
            tk.y = pack_h2(f01, f11);
            tk.z = pack_h2(f02, f12);
            tk.w = pack_h2(f03, f13);
            kv0 = make_uint2(pack_h2(f00, f01), pack_h2(f02, f03));
            kv1 = make_uint2(pack_h2(f10, f11), pack_h2(f12, f13));
        }

        if (cc < 7) {
            const size_t gan = (size_t)((cc + 1) * 32 + 2 * p_) * HW + wbase + pg;
            q0h = *(const uint2*)(qb + gan);
            q1h = *(const uint2*)(qb + gan + HW);
            k0h = *(const uint2*)(kb + gan);
            k1h = *(const uint2*)(kb + gan + HW);
        }

        *(uint4*)&sQb[p_ * QP_ST + pg] = tq;
        *(uint4*)&sKb[p_ * QP_ST + pg] = tk;
        *(uint2*)&sKv[(size_t)c0 * KV_ST + (pg >> 1)]       = kv0;
        *(uint2*)&sKv[(size_t)(c0 + 1) * KV_ST + (pg >> 1)] = kv1;
        __syncthreads();

#pragma unroll
        for (int ks = 0; ks < 2; ks++) {
            const int kp = ks * 8 + (lane & 3);
            const int mrow = wm * 16 + (lane >> 2);
            uint32_t a[4];
            a[0] = sQb[kp * QP_ST + mrow];
            a[1] = sQb[kp * QP_ST + mrow + 8];
            a[2] = sQb[(kp + 4) * QP_ST + mrow];
            a[3] = sQb[(kp + 4) * QP_ST + mrow + 8];
#pragma unroll
            for (int nb = 0; nb < 4; nb++) {
                const int ncol = wn * 32 + nb * 8 + (lane >> 2);
                uint32_t b0 = sKb[kp * QP_ST + ncol];
                uint32_t b1 = sKb[(kp + 4) * QP_ST + ncol];
                mmaf16(acc[nb], a, b0, b1);
            }
        }
    }

    // ================= register softmax =================
    const int rA = wm * 16 + (lane >> 2);
    const int rB = rA + 8;
    {
#pragma unroll
        for (int nb = 0; nb < 4; nb++)
#pragma unroll
            for (int r = 0; r < 4; r++) acc[nb][r] *= 0.0625f;

        float mA = acc[0][0], mB = acc[0][2];
#pragma unroll
        for (int nb = 0; nb < 4; nb++) {
            mA = fmaxf(mA, fmaxf(acc[nb][0], acc[nb][1]));
            mB = fmaxf(mB, fmaxf(acc[nb][2], acc[nb][3]));
        }
        mA = fmaxf(mA, __shfl_xor_sync(0xffffffffu, mA, 1));
        mA = fmaxf(mA, __shfl_xor_sync(0xffffffffu, mA, 2));
        mB = fmaxf(mB, __shfl_xor_sync(0xffffffffu, mB, 1));
        mB = fmaxf(mB, __shfl_xor_sync(0xffffffffu, mB, 2));
        __syncthreads();
        if ((lane & 3) == 0) {
            pmax[rA * 2 + wn] = mA;
            pmax[rB * 2 + wn] = mB;
        }
        __syncthreads();

        float MA = fmaxf(pmax[rA * 2], pmax[rA * 2 + 1]);
        float MB = fmaxf(pmax[rB * 2], pmax[rB * 2 + 1]);
        float sA = 0.f, sB = 0.f;
#pragma unroll
        for (int nb = 0; nb < 4; nb++) {
            acc[nb][0] = __expf(acc[nb][0] - MA);
            acc[nb][1] = __expf(acc[nb][1] - MA);
            acc[nb][2] = __expf(acc[nb][2] - MB);
            acc[nb][3] = __expf(acc[nb][3] - MB);
            sA += acc[nb][0] + acc[nb][1];
            sB += acc[nb][2] + acc[nb][3];
        }
        sA += __shfl_xor_sync(0xffffffffu, sA, 1);
        sA += __shfl_xor_sync(0xffffffffu, sA, 2);
        sB += __shfl_xor_sync(0xffffffffu, sB, 1);
        sB += __shfl_xor_sync(0xffffffffu, sB, 2);
        if ((lane & 3) == 0) {
            psum[rA * 2 + wn] = sA;
            psum[rB * 2 + wn] = sB;
        }
        __syncthreads();

        float invA = 1.f / (psum[rA * 2] + psum[rA * 2 + 1]);
        float invB = 1.f / (psum[rB * 2] + psum[rB * 2 + 1]);
#pragma unroll
        for (int nb = 0; nb < 4; nb++) {
            int pcol = wn * 16 + nb * 4 + (lane & 3);
            sPh[rA * PH_ST + pcol] = pack_h2(acc[nb][0] * invA, acc[nb][1] * invA);
            sPh[rB * PH_ST + pcol] = pack_h2(acc[nb][2] * invB, acc[nb][3] * invB);
        }
    }
    __syncthreads();

    // ================= Phase PV =================
    float* sO = (float*)sm;

    const int xc0 = tid >> 4;
    const int xr0 = tid & 15;
    const int xc1 = 16 + xc0;
    float4 xA, xB;
    {
        size_t ga = (size_t)bb * IMG + base_px +
                    (size_t)(xr0 >> 1) * 128 + (xr0 & 1) * 4;
        xA = *(const float4*)(xlo + ga + (size_t)xc0 * HW);
        xB = *(const float4*)(xlo + ga + (size_t)xc1 * HW);
    }

#pragma unroll 1
    for (int cc = 0; cc < 8; cc++) {
        float acc2[2][4];
#pragma unroll
        for (int nb = 0; nb < 2; nb++)
#pragma unroll
            for (int r = 0; r < 4; r++) acc2[nb][r] = 0.f;

#pragma unroll
        for (int ks = 0; ks < 4; ks++) {
            const int jp = ks * 8 + (lane & 3);
            const int i0 = wm * 16 + (lane >> 2);
            uint32_t a[4];
            a[0] = sPh[i0 * PH_ST + jp];
            a[1] = sPh[(i0 + 8) * PH_ST + jp];
            a[2] = sPh[i0 * PH_ST + jp + 4];
            a[3] = sPh[(i0 + 8) * PH_ST + jp + 4];
#pragma unroll
            for (int nb = 0; nb < 2; nb++) {
                const int c = cc * 32 + wn * 16 + nb * 8 + (lane >> 2);
                uint32_t b0 = sKv[c * KV_ST + jp];
                uint32_t b1 = sKv[c * KV_ST + jp + 4];
                mmaf16(acc2[nb], a, b0, b1);
            }
        }

        __syncthreads();

        {
            const int px = wm * 16 + (lane >> 2);
#pragma unroll
            for (int nb = 0; nb < 2; nb++) {
                const int chl = wn * 16 + nb * 8 + (lane & 3) * 2;
                sO[chl * SP_ST + px]           = acc2[nb][0];
                sO[(chl + 1) * SP_ST + px]     = acc2[nb][1];
                sO[chl * SP_ST + px + 8]       = acc2[nb][2];
                sO[(chl + 1) * SP_ST + px + 8] = acc2[nb][3];
            }
        }
        __syncthreads();

        {
            size_t gbase = (size_t)bb * IMG + base_px +
                           (size_t)(xr0 >> 1) * 128 + (xr0 & 1) * 4;
            int so_off = (xr0 >> 1) * 8 + (xr0 & 1) * 4;
            float4 o0 = *(const float4*)&sO[xc0 * SP_ST + so_off];
            float4 o1 = *(const float4*)&sO[xc1 * SP_ST + so_off];
            o0.x += xA.x; o0.y += xA.y; o0.z += xA.z; o0.w += xA.w;
            o1.x += xB.x; o1.y += xB.y; o1.z += xB.z; o1.w += xB.w;
            *(float4*)(outp + gbase + (size_t)(cc * 32 + xc0) * HW) = o0;
            *(float4*)(outp + gbase + (size_t)(cc * 32 + xc1) * HW) = o1;
            if (cc < 7) {
                xA = *(const float4*)(xlo + gbase + (size_t)((cc + 1) * 32 + xc0) * HW);
                xB = *(const float4*)(xlo + gbase + (size_t)((cc + 1) * 32 + xc1) * HW);
            }
        }
    }
}

// ---------------------------------------------------------------------------
// Launcher
// ---------------------------------------------------------------------------
extern "C" void kernel_launch(void* const* d_in, const int* in_sizes, int n_in,
                              void* d_out, int out_size)
{
    const float* x_low  = (const float*)d_in[0];
    const float* x_high = (const float*)d_in[1];
    const float* wq     = (const float*)d_in[2];
    const float* wk     = (const float*)d_in[3];
    const float* gq     = (const float*)d_in[4];
    const float* bq     = (const float*)d_in[5];
    const float* gk     = (const float*)d_in[6];
    const float* bk     = (const float*)d_in[7];
    float* outp = (float*)d_out;

    prep_afrag<<<256, 256>>>(wq, wk);

    cudaFuncSetAttribute(proj_mma,
                         cudaFuncAttributeMaxDynamicSharedMemorySize,
                         PJ_SMEM_BYTES);
    proj_mma<<<dim3(2, 1024, 2), 256, PJ_SMEM_BYTES>>>(x_low, x_high);

    stats_finalize<<<512, 128>>>();

    cudaFuncSetAttribute(attn_mma,
                         cudaFuncAttributeMaxDynamicSharedMemorySize,
                         AT_SMEM_BYTES);
    attn_mma<<<2048, 256, AT_SMEM_BYTES>>>(x_low, outp, gq, bq, gk, bk);
}

// round 15
// speedup vs baseline: 1.1494x; 1.0127x over previous
#include <cuda_runtime.h>
#include <cuda_fp16.h>
#include <cstdint>

// ---------------------------------------------------------------------------
// Problem constants
// ---------------------------------------------------------------------------
#define BATCH   8
#define CH      256
#define HW      16384
#define IMG     (CH * HW)
#define GROUPS  32
#define GSZ     (CH / GROUPS)
#define NPIX    64
#define EPS     1e-5f

// g_qraw/g_kraw: fp16, WINDOW-TILED pixel layout within each channel:
//   px' = window_id * 64 + (y&7)*8 + (x&7),  window_id = (y>>3)*16 + (x>>3)
static __device__ __half g_qraw[(size_t)BATCH * IMG];
static __device__ __half g_kraw[(size_t)BATCH * IMG];
static __device__ float g_mean[2 * BATCH * GROUPS];
static __device__ float g_rstd[2 * BATCH * GROUPS];
// Pre-permuted fp16 A fragments (half2 k-pairs, m16n8k16 layout)
static __device__ uint32_t g_afragh[65536];
// per-(tensor,batch,group) x per-pixel-tile partial (sum, sumsq)
static __device__ float g_psum[512 * 256];

// ---------------------------------------------------------------------------
// helpers
// ---------------------------------------------------------------------------
__device__ __forceinline__ uint32_t pack_h2(float x, float y) {
    __half2 h = __float22half2_rn(make_float2(x, y));
    return *(uint32_t*)&h;
}
__device__ __forceinline__ float4 h4_to_f4(uint2 v) {
    float2 a = __half22float2(*(__half2*)&v.x);
    float2 b = __half22float2(*(__half2*)&v.y);
    return make_float4(a.x, a.y, b.x, b.y);
}

__device__ __forceinline__ void mmaf16(float d[4], const uint32_t a[4],
                                       uint32_t b0, uint32_t b1) {
    asm volatile(
        "mma.sync.aligned.m16n8k16.row.col.f32.f16.f16.f32 "
        "{%0,%1,%2,%3}, {%4,%5,%6,%7}, {%8,%9}, {%0,%1,%2,%3};"
        : "+f"(d[0]), "+f"(d[1]), "+f"(d[2]), "+f"(d[3])
        : "r"(a[0]), "r"(a[1]), "r"(a[2]), "r"(a[3]), "r"(b0), "r"(b1));
}

__device__ __forceinline__ uint32_t smem_u32(const void* p) {
    uint32_t a;
    asm("{ .reg .u64 t; cvta.to.shared.u64 t, %1; cvt.u32.u64 %0, t; }"
        : "=r"(a) : "l"(p));
    return a;
}

__device__ __forceinline__ void cpa16(uint32_t dst, const void* src) {
    asm volatile("cp.async.cg.shared.global [%0], [%1], 16;"
                 :: "r"(dst), "l"(src));
}
#define CPA_COMMIT() asm volatile("cp.async.commit_group;" ::: "memory")
#define CPA_WAIT(N)  asm volatile("cp.async.wait_group %0;" :: "n"(N) : "memory")

// ---------------------------------------------------------------------------
// Kernel 0: build fragment-ordered fp16 A operand (half2 k-pairs).
// ---------------------------------------------------------------------------
__global__ void __launch_bounds__(256) prep_afrag(
    const float* __restrict__ wq, const float* __restrict__ wk)
{
    int idx = blockIdx.x * 256 + threadIdx.x;   // 0..65535
    int reg   = idx & 3;
    int lane  = (idx >> 2) & 31;
    int ks    = (idx >> 7) & 1;
    int mbg   = (idx >> 8) & 7;
    int chunk = (idx >> 11) & 7;
    int mt    = (idx >> 14) & 1;
    int t     = (idx >> 15) & 1;

    int m  = mt * 128 + mbg * 16 + (reg & 1) * 8 + (lane >> 2);
    int kp = (lane & 3) + ((reg >> 1) & 1) * 4;
    int k  = chunk * 32 + ks * 16 + kp * 2;
    const float* W = t ? wk : wq;
    g_afragh[idx] = pack_h2(W[m * CH + k], W[m * CH + k + 1]);
}

// ---------------------------------------------------------------------------
// Kernel 1: projection GEMM via fp16 m16n8k16 + fused GroupNorm partials.
// R15: BOTH operands flow through depth-4 cp.async rings (issue-ahead 3
// chunks). B is staged as RAW fp32 X rows (stride 132, conflict-free
// fragment reads); half conversion happens in the fragment load via
// __floats2half2_rn — bitwise-identical math to R14. One barrier per chunk,
// no synchronous gmem, no STS in the hot loop.
// Dynamic smem: A ring 4x2048 words + B ring 4x4224 words = 100,352 B.
// ---------------------------------------------------------------------------
#define BF_ST 132
#define PJ_B  8192
#define PJ_SMEM_BYTES ((8192 + 4 * 4224) * 4)   // 100,352 bytes

__global__ void __launch_bounds__(256, 2) proj_mma(
    const float* __restrict__ xlo, const float* __restrict__ xhi)
{
    extern __shared__ __align__(16) uint32_t smu[];
    const uint32_t sbase = smem_u32(smu);

    const int tid  = threadIdx.x;
    const int wid  = tid >> 5;
    const int lane = tid & 31;

    const int mt = blockIdx.x;
    const int tz = blockIdx.z;
    const float* X = tz ? xhi : xlo;
    __half*      Y = tz ? g_kraw : g_qraw;

    const int bb = blockIdx.y >> 7;
    const int yrow = blockIdx.y & 127;
    const int p0 = yrow << 7;
    const int m0 = mt << 7;

    const float* Xb = X + (size_t)bb * IMG + p0;
    const uint32_t* Agh = g_afragh + (size_t)(tz * 2 + mt) * 16384;

    const int wm = wid >> 2;
    const int wn = wid & 3;

    float acc[4][4][4];
#pragma unroll
    for (int i = 0; i < 4; i++)
#pragma unroll
        for (int j = 0; j < 4; j++)
#pragma unroll
            for (int r = 0; r < 4; r++) acc[i][j][r] = 0.f;

    // ---- prologue: issue chunks 0..2 (A fragments + raw fp32 B rows) ----
#pragma unroll
    for (int pc = 0; pc < 3; pc++) {
        const uint32_t* Agc = Agh + pc * 2048;
#pragma unroll
        for (int i = 0; i < 2; i++) {
            int idx = i * 256 + tid;
            cpa16(sbase + (pc * 2048 + idx * 4) * 4, Agc + idx * 4);
        }
#pragma unroll
        for (int i = 0; i < 4; i++) {
            int idx = i * 256 + tid;
            int row = idx >> 5, c4 = idx & 31;
            cpa16(sbase + (PJ_B + pc * 4224 + row * BF_ST + c4 * 4) * 4,
                  Xb + (size_t)(pc * 32 + row) * HW + c4 * 4);
        }
        CPA_COMMIT();
    }

#pragma unroll 1
    for (int c = 0; c < 8; c++) {
        // wait for chunk c's group (groups are FIFO; see issue schedule)
        if (c < 6)      CPA_WAIT(2);
        else if (c == 6) CPA_WAIT(1);
        else             CPA_WAIT(0);
        __syncthreads();   // publish chunk c; slot (c+3)&3's readers done

        // issue chunk c+3 into ring slot (c+3)&3 (read at iter c-1, safe)
        if (c < 5) {
            const int sl = (c + 3) & 3;
            const uint32_t* Agc = Agh + (c + 3) * 2048;
#pragma unroll
            for (int i = 0; i < 2; i++) {
                int idx = i * 256 + tid;
                cpa16(sbase + (sl * 2048 + idx * 4) * 4, Agc + idx * 4);
            }
#pragma unroll
            for (int i = 0; i < 4; i++) {
                int idx = i * 256 + tid;
                int row = idx >> 5, c4 = idx & 31;
                cpa16(sbase + (PJ_B + sl * 4224 + row * BF_ST + c4 * 4) * 4,
                      Xb + (size_t)((c + 3) * 32 + row) * HW + c4 * 4);
            }
            CPA_COMMIT();
        }

        const uint32_t* Ab = smu + (c & 3) * 2048;
        const float*    Bf = (const float*)(smu + PJ_B + (c & 3) * 4224);

#pragma unroll
        for (int ks = 0; ks < 2; ks++) {
            uint32_t afr[4][4];
#pragma unroll
            for (int mb = 0; mb < 4; mb++) {
                int mbg = wm * 4 + mb;
                *(uint4*)afr[mb] =
                    *(const uint4*)&Ab[(mbg * 2 + ks) * 128 + lane * 4];
            }
            const int kr2  = (ks * 8 + (lane & 3)) * 2;   // k row (even)
            const int ncol = wn * 32 + (lane >> 2);
#pragma unroll
            for (int nb = 0; nb < 4; nb++) {
                const int nc = ncol + nb * 8;
                uint32_t b0 = pack_h2(Bf[kr2 * BF_ST + nc],
                                      Bf[(kr2 + 1) * BF_ST + nc]);
                uint32_t b1 = pack_h2(Bf[(kr2 + 8) * BF_ST + nc],
                                      Bf[(kr2 + 9) * BF_ST + nc]);
#pragma unroll
                for (int mb = 0; mb < 4; mb++)
                    mmaf16(acc[mb][nb], afr[mb], b0, b1);
            }
        }
    }

    // ---- fused GroupNorm partial statistics ----
    __shared__ float red[16][4][2];
#pragma unroll
    for (int mb = 0; mb < 4; mb++) {
        float sE = 0.f, qE = 0.f, sO_ = 0.f, qO = 0.f;
#pragma unroll
        for (int nb = 0; nb < 4; nb++) {
            sE += acc[mb][nb][0] + acc[mb][nb][1];
            qE += acc[mb][nb][0] * acc[mb][nb][0] + acc[mb][nb][1] * acc[mb][nb][1];
            sO_ += acc[mb][nb][2] + acc[mb][nb][3];
            qO += acc[mb][nb][2] * acc[mb][nb][2] + acc[mb][nb][3] * acc[mb][nb][3];
        }
#pragma unroll
        for (int off = 16; off; off >>= 1) {
            sE += __shfl_xor_sync(0xffffffffu, sE, off);
            qE += __shfl_xor_sync(0xffffffffu, qE, off);
            sO_ += __shfl_xor_sync(0xffffffffu, sO_, off);
            qO += __shfl_xor_sync(0xffffffffu, qO, off);
        }
        if (lane == 0) {
            int gl = wm * 8 + mb * 2;
            red[gl][wn][0] = sE;     red[gl][wn][1] = qE;
            red[gl + 1][wn][0] = sO_; red[gl + 1][wn][1] = qO;
        }
    }
    __syncthreads();
    if (tid < 32) {
        int gl = tid >> 1, sq = tid & 1;
        float v = red[gl][0][sq] + red[gl][1][sq] + red[gl][2][sq] + red[gl][3][sq];
        g_psum[((size_t)((tz * 8 + bb) * 32) + mt * 16 + gl) * 256 + yrow * 2 + sq] = v;
    }

    // ---- epilogue: fp16 window-tiled store ----
    const int base2 = (yrow >> 3) * 1024 + (yrow & 7) * 8;
    __half* Yb = Y + (size_t)bb * IMG + base2;
    const int rl = lane >> 2;
    const int cl = (lane & 3) * 2;
#pragma unroll
    for (int mb = 0; mb < 4; mb++) {
        int mrow = m0 + wm * 64 + mb * 16 + rl;
#pragma unroll
        for (int nb = 0; nb < 4; nb++) {
            int noff = (wn * 4 + nb) * 64 + cl;
            __half2 v0 = __floats2half2_rn(acc[mb][nb][0], acc[mb][nb][1]);
            __half2 v1 = __floats2half2_rn(acc[mb][nb][2], acc[mb][nb][3]);
            *(__half2*)(Yb + (size_t)mrow * HW + noff)       = v0;
            *(__half2*)(Yb + (size_t)(mrow + 8) * HW + noff) = v1;
        }
    }
}

// ---------------------------------------------------------------------------
// Kernel 2: GroupNorm stats finalize.
// ---------------------------------------------------------------------------
__global__ void __launch_bounds__(128) stats_finalize()
{
    const int id  = blockIdx.x;
    const int tid = threadIdx.x;
    const float* p = g_psum + (size_t)id * 256;

    __shared__ float rs[128], rq[128];
    rs[tid] = p[tid * 2];
    rq[tid] = p[tid * 2 + 1];
    __syncthreads();
    for (int o = 64; o; o >>= 1) {
        if (tid < o) { rs[tid] += rs[tid + o]; rq[tid] += rq[tid + o]; }
        __syncthreads();
    }
    if (tid == 0) {
        const float invN = 1.f / (float)(GSZ * HW);
        float m   = rs[0] * invN;
        float var = rq[0] * invN - m * m;
        g_mean[id] = m;
        g_rstd[id] = rsqrtf(var + EPS);
    }
}

// ---------------------------------------------------------------------------
// Kernel 3: windowed attention (identical to R14).
// ---------------------------------------------------------------------------
#define QP_ST 72
#define SP_ST 68
#define PH_ST 36
#define KV_ST 36
#define AT_PH   2304
#define AT_KV   4608
#define AT_PMAX 13824
#define AT_PSUM 13952
#define AT_SMEM_BYTES (14080 * 4)

__global__ void __launch_bounds__(256) attn_mma(
    const float* __restrict__ xlo, float* __restrict__ outp,
    const float* __restrict__ gq, const float* __restrict__ bq,
    const float* __restrict__ gk, const float* __restrict__ bk)
{
    extern __shared__ __align__(16) uint32_t sm[];
    uint32_t* sPh = sm + AT_PH;
    uint32_t* sKv = sm + AT_KV;
    float*    pmax = (float*)(sm + AT_PMAX);
    float*    psum = (float*)(sm + AT_PSUM);

    const int tid  = threadIdx.x;
    const int wid  = tid >> 5;
    const int lane = tid & 31;

    const int bb  = blockIdx.x >> 8;
    const int wnd = blockIdx.x & 255;
    const int base_px = ((wnd >> 4) << 3) * 128 + ((wnd & 15) << 3);
    const int wbase = wnd * 64;

    const __half* qb = g_qraw + (size_t)bb * IMG;
    const __half* kb = g_kraw + (size_t)bb * IMG;

    const int wm = wid & 3;
    const int wn = wid >> 2;

    const int p_  = tid >> 4;
    const int pg  = (tid & 15) * 4;

    float acc[4][4];
#pragma unroll
    for (int i = 0; i < 4; i++)
#pragma unroll
        for (int j = 0; j < 4; j++) acc[i][j] = 0.f;

    uint2 q0h, q1h, k0h, k1h;
    {
        const size_t ga0 = (size_t)(2 * p_) * HW + wbase + pg;
        q0h = *(const uint2*)(qb + ga0);
        q1h = *(const uint2*)(qb + ga0 + HW);
        k0h = *(const uint2*)(kb + ga0);
        k1h = *(const uint2*)(kb + ga0 + HW);
    }

    // ================= Phase S (ping-pong staging, 1 barrier/chunk) =======
#pragma unroll 1
    for (int cc = 0; cc < 8; cc++) {
        uint32_t* sQb = sm + (cc & 1) * 2304;
        uint32_t* sKb = sQb + 1152;

        const int c0 = cc * 32 + 2 * p_;
        const int g  = c0 >> 3;
        float4 q0 = h4_to_f4(q0h), q1 = h4_to_f4(q1h);
        float4 k0 = h4_to_f4(k0h), k1 = h4_to_f4(k1h);
        uint4 tq, tk;
        uint2 kv0, kv1;
        {
            float rq_ = g_rstd[bb * 32 + g], mq_ = g_mean[bb * 32 + g];
            float a0 = rq_ * gq[c0],     d0 = fmaf(-mq_, a0, bq[c0]);
            float a1 = rq_ * gq[c0 + 1], d1 = fmaf(-mq_, a1, bq[c0 + 1]);
            tq.x = pack_h2(fmaf(q0.x, a0, d0), fmaf(q1.x, a1, d1));
            tq.y = pack_h2(fmaf(q0.y, a0, d0), fmaf(q1.y, a1, d1));
            tq.z = pack_h2(fmaf(q0.z, a0, d0), fmaf(q1.z, a1, d1));
            tq.w = pack_h2(fmaf(q0.w, a0, d0), fmaf(q1.w, a1, d1));
        }
        {
            float rk_ = g_rstd[256 + bb * 32 + g], mk_ = g_mean[256 + bb * 32 + g];
            float a0 = rk_ * gk[c0],     d0 = fmaf(-mk_, a0, bk[c0]);
            float a1 = rk_ * gk[c0 + 1], d1 = fmaf(-mk_, a1, bk[c0 + 1]);
            float f00 = fmaf(k0.x, a0, d0), f01 = fmaf(k0.y, a0, d0);
            float f02 = fmaf(k0.z, a0, d0), f03 = fmaf(k0.w, a0, d0);
            float f10 = fmaf(k1.x, a1, d1), f11 = fmaf(k1.y, a1, d1);
            float f12 = fmaf(k1.z, a1, d1), f13 = fmaf(k1.w, a1, d1);
            tk.x = pack_h2(f00, f10);
            tk.y = pack_h2(f01, f11);
            tk.z = pack_h2(f02, f12);
            tk.w = pack_h2(f03, f13);
            kv0 = make_uint2(pack_h2(f00, f01), pack_h2(f02, f03));
            kv1 = make_uint2(pack_h2(f10, f11), pack_h2(f12, f13));
        }

        if (cc < 7) {
            const size_t gan = (size_t)((cc + 1) * 32 + 2 * p_) * HW + wbase + pg;
            q0h = *(const uint2*)(qb + gan);
            q1h = *(const uint2*)(qb + gan + HW);
            k0h = *(const uint2*)(kb + gan);
            k1h = *(const uint2*)(kb + gan + HW);
        }

        *(uint4*)&sQb[p_ * QP_ST + pg] = tq;
        *(uint4*)&sKb[p_ * QP_ST + pg] = tk;
        *(uint2*)&sKv[(size_t)c0 * KV_ST + (pg >> 1)]       = kv0;
        *(uint2*)&sKv[(size_t)(c0 + 1) * KV_ST + (pg >> 1)] = kv1;
        __syncthreads();

#pragma unroll
        for (int ks = 0; ks < 2; ks++) {
            const int kp = ks * 8 + (lane & 3);
            const int mrow = wm * 16 + (lane >> 2);
            uint32_t a[4];
            a[0] = sQb[kp * QP_ST + mrow];
            a[1] = sQb[kp * QP_ST + mrow + 8];
            a[2] = sQb[(kp + 4) * QP_ST + mrow];
            a[3] = sQb[(kp + 4) * QP_ST + mrow + 8];
#pragma unroll
            for (int nb = 0; nb < 4; nb++) {
                const int ncol = wn * 32 + nb * 8 + (lane >> 2);
                uint32_t b0 = sKb[kp * QP_ST + ncol];
                uint32_t b1 = sKb[(kp + 4) * QP_ST + ncol];
                mmaf16(acc[nb], a, b0, b1);
            }
        }
    }

    // ================= register softmax =================
    const int rA = wm * 16 + (lane >> 2);
    const int rB = rA + 8;
    {
#pragma unroll
        for (int nb = 0; nb < 4; nb++)
#pragma unroll
            for (int r = 0; r < 4; r++) acc[nb][r] *= 0.0625f;

        float mA = acc[0][0], mB = acc[0][2];
#pragma unroll
        for (int nb = 0; nb < 4; nb++) {
            mA = fmaxf(mA, fmaxf(acc[nb][0], acc[nb][1]));
            mB = fmaxf(mB, fmaxf(acc[nb][2], acc[nb][3]));
        }
        mA = fmaxf(mA, __shfl_xor_sync(0xffffffffu, mA, 1));
        mA = fmaxf(mA, __shfl_xor_sync(0xffffffffu, mA, 2));
        mB = fmaxf(mB, __shfl_xor_sync(0xffffffffu, mB, 1));
        mB = fmaxf(mB, __shfl_xor_sync(0xffffffffu, mB, 2));
        __syncthreads();
        if ((lane & 3) == 0) {
            pmax[rA * 2 + wn] = mA;
            pmax[rB * 2 + wn] = mB;
        }
        __syncthreads();

        float MA = fmaxf(pmax[rA * 2], pmax[rA * 2 + 1]);
        float MB = fmaxf(pmax[rB * 2], pmax[rB * 2 + 1]);
        float sA = 0.f, sB = 0.f;
#pragma unroll
        for (int nb = 0; nb < 4; nb++) {
            acc[nb][0] = __expf(acc[nb][0] - MA);
            acc[nb][1] = __expf(acc[nb][1] - MA);
            acc[nb][2] = __expf(acc[nb][2] - MB);
            acc[nb][3] = __expf(acc[nb][3] - MB);
            sA += acc[nb][0] + acc[nb][1];
            sB += acc[nb][2] + acc[nb][3];
        }
        sA += __shfl_xor_sync(0xffffffffu, sA, 1);
        sA += __shfl_xor_sync(0xffffffffu, sA, 2);
        sB += __shfl_xor_sync(0xffffffffu, sB, 1);
        sB += __shfl_xor_sync(0xffffffffu, sB, 2);
        if ((lane & 3) == 0) {
            psum[rA * 2 + wn] = sA;
            psum[rB * 2 + wn] = sB;
        }
        __syncthreads();

        float invA = 1.f / (psum[rA * 2] + psum[rA * 2 + 1]);
        float invB = 1.f / (psum[rB * 2] + psum[rB * 2 + 1]);
#pragma unroll
        for (int nb = 0; nb < 4; nb++) {
            int pcol = wn * 16 + nb * 4 + (lane & 3);
            sPh[rA * PH_ST + pcol] = pack_h2(acc[nb][0] * invA, acc[nb][1] * invA);
            sPh[rB * PH_ST + pcol] = pack_h2(acc[nb][2] * invB, acc[nb][3] * invB);
        }
    }
    __syncthreads();

    // ================= Phase PV =================
    float* sO = (float*)sm;

    const int xc0 = tid >> 4;
    const int xr0 = tid & 15;
    const int xc1 = 16 + xc0;
    float4 xA, xB;
    {
        size_t ga = (size_t)bb * IMG + base_px +
                    (size_t)(xr0 >> 1) * 128 + (xr0 & 1) * 4;
        xA = *(const float4*)(xlo + ga + (size_t)xc0 * HW);
        xB = *(const float4*)(xlo + ga + (size_t)xc1 * HW);
    }

#pragma unroll 1
    for (int cc = 0; cc < 8; cc++) {
        float acc2[2][4];
#pragma unroll
        for (int nb = 0; nb < 2; nb++)
#pragma unroll
            for (int r = 0; r < 4; r++) acc2[nb][r] = 0.f;

#pragma unroll
        for (int ks = 0; ks < 4; ks++) {
            const int jp = ks * 8 + (lane & 3);
            const int i0 = wm * 16 + (lane >> 2);
            uint32_t a[4];
            a[0] = sPh[i0 * PH_ST + jp];
            a[1] = sPh[(i0 + 8) * PH_ST + jp];
            a[2] = sPh[i0 * PH_ST + jp + 4];
            a[3] = sPh[(i0 + 8) * PH_ST + jp + 4];
#pragma unroll
            for (int nb = 0; nb < 2; nb++) {
                const int c = cc * 32 + wn * 16 + nb * 8 + (lane >> 2);
                uint32_t b0 = sKv[c * KV_ST + jp];
                uint32_t b1 = sKv[c * KV_ST + jp + 4];
                mmaf16(acc2[nb], a, b0, b1);
            }
        }

        __syncthreads();

        {
            const int px = wm * 16 + (lane >> 2);
#pragma unroll
            for (int nb = 0; nb < 2; nb++) {
                const int chl = wn * 16 + nb * 8 + (lane & 3) * 2;
                sO[chl * SP_ST + px]           = acc2[nb][0];
                sO[(chl + 1) * SP_ST + px]     = acc2[nb][1];
                sO[chl * SP_ST + px + 8]       = acc2[nb][2];
                sO[(chl + 1) * SP_ST + px + 8] = acc2[nb][3];
            }
        }
        __syncthreads();

        {
            size_t gbase = (size_t)bb * IMG + base_px +
                           (size_t)(xr0 >> 1) * 128 + (xr0 & 1) * 4;
            int so_off = (xr0 >> 1) * 8 + (xr0 & 1) * 4;
            float4 o0 = *(const float4*)&sO[xc0 * SP_ST + so_off];
            float4 o1 = *(const float4*)&sO[xc1 * SP_ST + so_off];
            o0.x += xA.x; o0.y += xA.y; o0.z += xA.z; o0.w += xA.w;
            o1.x += xB.x; o1.y += xB.y; o1.z += xB.z; o1.w += xB.w;
            *(float4*)(outp + gbase + (size_t)(cc * 32 + xc0) * HW) = o0;
            *(float4*)(outp + gbase + (size_t)(cc * 32 + xc1) * HW) = o1;
            if (cc < 7) {
                xA = *(const float4*)(xlo + gbase + (size_t)((cc + 1) * 32 + xc0) * HW);
                xB = *(const float4*)(xlo + gbase + (size_t)((cc + 1) * 32 + xc1) * HW);
            }
        }
    }
}

// ---------------------------------------------------------------------------
// Launcher
// ---------------------------------------------------------------------------
extern "C" void kernel_launch(void* const* d_in, const int* in_sizes, int n_in,
                              void* d_out, int out_size)
{
    const float* x_low  = (const float*)d_in[0];
    const float* x_high = (const float*)d_in[1];
    const float* wq     = (const float*)d_in[2];
    const float* wk     = (const float*)d_in[3];
    const float* gq     = (const float*)d_in[4];
    const float* bq     = (const float*)d_in[5];
    const float* gk     = (const float*)d_in[6];
    const float* bk     = (const float*)d_in[7];
    float* outp = (float*)d_out;

    prep_afrag<<<256, 256>>>(wq, wk);

    cudaFuncSetAttribute(proj_mma,
                         cudaFuncAttributeMaxDynamicSharedMemorySize,
                         PJ_SMEM_BYTES);
    proj_mma<<<dim3(2, 1024, 2), 256, PJ_SMEM_BYTES>>>(x_low, x_high);

    stats_finalize<<<512, 128>>>();

    cudaFuncSetAttribute(attn_mma,
                         cudaFuncAttributeMaxDynamicSharedMemorySize,
                         AT_SMEM_BYTES);
    attn_mma<<<2048, 256, AT_SMEM_BYTES>>>(x_low, outp, gq, bq, gk, bk);
}

// round 16
// speedup vs baseline: 1.1523x; 1.0025x over previous
#include <cuda_runtime.h>
#include <cuda_fp16.h>
#include <cstdint>

// ---------------------------------------------------------------------------
// Problem constants
// ---------------------------------------------------------------------------
#define BATCH   8
#define CH      256
#define HW      16384
#define IMG     (CH * HW)
#define GROUPS  32
#define GSZ     (CH / GROUPS)
#define NPIX    64
#define EPS     1e-5f

// g_qraw/g_kraw: fp16, WINDOW-TILED pixel layout within each channel:
//   px' = window_id * 64 + (y&7)*8 + (x&7),  window_id = (y>>3)*16 + (x>>3)
static __device__ __half g_qraw[(size_t)BATCH * IMG];
static __device__ __half g_kraw[(size_t)BATCH * IMG];
static __device__ float g_mean[2 * BATCH * GROUPS];
static __device__ float g_rstd[2 * BATCH * GROUPS];
// Pre-permuted fp16 A fragments (half2 k-pairs, m16n8k16 layout)
static __device__ uint32_t g_afragh[65536];
// per-(tensor,batch,group) x per-pixel-tile partial (sum, sumsq)
static __device__ float g_psum[512 * 256];

// ---------------------------------------------------------------------------
// helpers
// ---------------------------------------------------------------------------
__device__ __forceinline__ uint32_t pack_h2(float x, float y) {
    __half2 h = __float22half2_rn(make_float2(x, y));
    return *(uint32_t*)&h;
}
__device__ __forceinline__ float4 h4_to_f4(uint2 v) {
    float2 a = __half22float2(*(__half2*)&v.x);
    float2 b = __half22float2(*(__half2*)&v.y);
    return make_float4(a.x, a.y, b.x, b.y);
}

__device__ __forceinline__ void mmaf16(float d[4], const uint32_t a[4],
                                       uint32_t b0, uint32_t b1) {
    asm volatile(
        "mma.sync.aligned.m16n8k16.row.col.f32.f16.f16.f32 "
        "{%0,%1,%2,%3}, {%4,%5,%6,%7}, {%8,%9}, {%0,%1,%2,%3};"
        : "+f"(d[0]), "+f"(d[1]), "+f"(d[2]), "+f"(d[3])
        : "r"(a[0]), "r"(a[1]), "r"(a[2]), "r"(a[3]), "r"(b0), "r"(b1));
}

__device__ __forceinline__ uint32_t smem_u32(const void* p) {
    uint32_t a;
    asm("{ .reg .u64 t; cvta.to.shared.u64 t, %1; cvt.u32.u64 %0, t; }"
        : "=r"(a) : "l"(p));
    return a;
}

__device__ __forceinline__ void cpa16(uint32_t dst, const void* src) {
    asm volatile("cp.async.cg.shared.global [%0], [%1], 16;"
                 :: "r"(dst), "l"(src));
}
#define CPA_COMMIT() asm volatile("cp.async.commit_group;" ::: "memory")
#define CPA_WAIT(N)  asm volatile("cp.async.wait_group %0;" :: "n"(N) : "memory")

// ---------------------------------------------------------------------------
// Kernel 0: build fragment-ordered fp16 A operand (half2 k-pairs).
// ---------------------------------------------------------------------------
__global__ void __launch_bounds__(256) prep_afrag(
    const float* __restrict__ wq, const float* __restrict__ wk)
{
    int idx = blockIdx.x * 256 + threadIdx.x;   // 0..65535
    int reg   = idx & 3;
    int lane  = (idx >> 2) & 31;
    int ks    = (idx >> 7) & 1;
    int mbg   = (idx >> 8) & 7;
    int chunk = (idx >> 11) & 7;
    int mt    = (idx >> 14) & 1;
    int t     = (idx >> 15) & 1;

    int m  = mt * 128 + mbg * 16 + (reg & 1) * 8 + (lane >> 2);
    int kp = (lane & 3) + ((reg >> 1) & 1) * 4;
    int k  = chunk * 32 + ks * 16 + kp * 2;
    const float* W = t ? wk : wq;
    g_afragh[idx] = pack_h2(W[m * CH + k], W[m * CH + k + 1]);
}

// ---------------------------------------------------------------------------
// Kernel 1: projection GEMM via fp16 m16n8k16 + fused GroupNorm partials.
// R16: identical structure to R15 (depth-4 async rings for A and B,
// raw-fp32 B with in-fragment conversion), plus STREAMING store hints
// (__stcs) on the Y epilogue — Y is consumed a whole kernel later, so
// evict-first keeps L2 for the X mt-pair reuse window.
// ---------------------------------------------------------------------------
#define BF_ST 132
#define PJ_B  8192
#define PJ_SMEM_BYTES ((8192 + 4 * 4224) * 4)   // 100,352 bytes

__global__ void __launch_bounds__(256, 2) proj_mma(
    const float* __restrict__ xlo, const float* __restrict__ xhi)
{
    extern __shared__ __align__(16) uint32_t smu[];
    const uint32_t sbase = smem_u32(smu);

    const int tid  = threadIdx.x;
    const int wid  = tid >> 5;
    const int lane = tid & 31;

    const int mt = blockIdx.x;
    const int tz = blockIdx.z;
    const float* X = tz ? xhi : xlo;
    __half*      Y = tz ? g_kraw : g_qraw;

    const int bb = blockIdx.y >> 7;
    const int yrow = blockIdx.y & 127;
    const int p0 = yrow << 7;
    const int m0 = mt << 7;

    const float* Xb = X + (size_t)bb * IMG + p0;
    const uint32_t* Agh = g_afragh + (size_t)(tz * 2 + mt) * 16384;

    const int wm = wid >> 2;
    const int wn = wid & 3;

    float acc[4][4][4];
#pragma unroll
    for (int i = 0; i < 4; i++)
#pragma unroll
        for (int j = 0; j < 4; j++)
#pragma unroll
            for (int r = 0; r < 4; r++) acc[i][j][r] = 0.f;

    // ---- prologue: issue chunks 0..2 (A fragments + raw fp32 B rows) ----
#pragma unroll
    for (int pc = 0; pc < 3; pc++) {
        const uint32_t* Agc = Agh + pc * 2048;
#pragma unroll
        for (int i = 0; i < 2; i++) {
            int idx = i * 256 + tid;
            cpa16(sbase + (pc * 2048 + idx * 4) * 4, Agc + idx * 4);
        }
#pragma unroll
        for (int i = 0; i < 4; i++) {
            int idx = i * 256 + tid;
            int row = idx >> 5, c4 = idx & 31;
            cpa16(sbase + (PJ_B + pc * 4224 + row * BF_ST + c4 * 4) * 4,
                  Xb + (size_t)(pc * 32 + row) * HW + c4 * 4);
        }
        CPA_COMMIT();
    }

#pragma unroll 1
    for (int c = 0; c < 8; c++) {
        // wait for chunk c's group (groups are FIFO; see issue schedule)
        if (c < 6)      CPA_WAIT(2);
        else if (c == 6) CPA_WAIT(1);
        else             CPA_WAIT(0);
        __syncthreads();   // publish chunk c; slot (c+3)&3's readers done

        // issue chunk c+3 into ring slot (c+3)&3 (read at iter c-1, safe)
        if (c < 5) {
            const int sl = (c + 3) & 3;
            const uint32_t* Agc = Agh + (c + 3) * 2048;
#pragma unroll
            for (int i = 0; i < 2; i++) {
                int idx = i * 256 + tid;
                cpa16(sbase + (sl * 2048 + idx * 4) * 4, Agc + idx * 4);
            }
#pragma unroll
            for (int i = 0; i < 4; i++) {
                int idx = i * 256 + tid;
                int row = idx >> 5, c4 = idx & 31;
                cpa16(sbase + (PJ_B + sl * 4224 + row * BF_ST + c4 * 4) * 4,
                      Xb + (size_t)((c + 3) * 32 + row) * HW + c4 * 4);
            }
            CPA_COMMIT();
        }

        const uint32_t* Ab = smu + (c & 3) * 2048;
        const float*    Bf = (const float*)(smu + PJ_B + (c & 3) * 4224);

#pragma unroll
        for (int ks = 0; ks < 2; ks++) {
            uint32_t afr[4][4];
#pragma unroll
            for (int mb = 0; mb < 4; mb++) {
                int mbg = wm * 4 + mb;
                *(uint4*)afr[mb] =
                    *(const uint4*)&Ab[(mbg * 2 + ks) * 128 + lane * 4];
            }
            const int kr2  = (ks * 8 + (lane & 3)) * 2;   // k row (even)
            const int ncol = wn * 32 + (lane >> 2);
#pragma unroll
            for (int nb = 0; nb < 4; nb++) {
                const int nc = ncol + nb * 8;
                uint32_t b0 = pack_h2(Bf[kr2 * BF_ST + nc],
                                      Bf[(kr2 + 1) * BF_ST + nc]);
                uint32_t b1 = pack_h2(Bf[(kr2 + 8) * BF_ST + nc],
                                      Bf[(kr2 + 9) * BF_ST + nc]);
#pragma unroll
                for (int mb = 0; mb < 4; mb++)
                    mmaf16(acc[mb][nb], afr[mb], b0, b1);
            }
        }
    }

    // ---- fused GroupNorm partial statistics ----
    __shared__ float red[16][4][2];
#pragma unroll
    for (int mb = 0; mb < 4; mb++) {
        float sE = 0.f, qE = 0.f, sO_ = 0.f, qO = 0.f;
#pragma unroll
        for (int nb = 0; nb < 4; nb++) {
            sE += acc[mb][nb][0] + acc[mb][nb][1];
            qE += acc[mb][nb][0] * acc[mb][nb][0] + acc[mb][nb][1] * acc[mb][nb][1];
            sO_ += acc[mb][nb][2] + acc[mb][nb][3];
            qO += acc[mb][nb][2] * acc[mb][nb][2] + acc[mb][nb][3] * acc[mb][nb][3];
        }
#pragma unroll
        for (int off = 16; off; off >>= 1) {
            sE += __shfl_xor_sync(0xffffffffu, sE, off);
            qE += __shfl_xor_sync(0xffffffffu, qE, off);
            sO_ += __shfl_xor_sync(0xffffffffu, sO_, off);
            qO += __shfl_xor_sync(0xffffffffu, qO, off);
        }
        if (lane == 0) {
            int gl = wm * 8 + mb * 2;
            red[gl][wn][0] = sE;     red[gl][wn][1] = qE;
            red[gl + 1][wn][0] = sO_; red[gl + 1][wn][1] = qO;
        }
    }
    __syncthreads();
    if (tid < 32) {
        int gl = tid >> 1, sq = tid & 1;
        float v = red[gl][0][sq] + red[gl][1][sq] + red[gl][2][sq] + red[gl][3][sq];
        g_psum[((size_t)((tz * 8 + bb) * 32) + mt * 16 + gl) * 256 + yrow * 2 + sq] = v;
    }

    // ---- epilogue: fp16 window-tiled store (streaming: used 1 kernel later)
    const int base2 = (yrow >> 3) * 1024 + (yrow & 7) * 8;
    __half* Yb = Y + (size_t)bb * IMG + base2;
    const int rl = lane >> 2;
    const int cl = (lane & 3) * 2;
#pragma unroll
    for (int mb = 0; mb < 4; mb++) {
        int mrow = m0 + wm * 64 + mb * 16 + rl;
#pragma unroll
        for (int nb = 0; nb < 4; nb++) {
            int noff = (wn * 4 + nb) * 64 + cl;
            __half2 v0 = __floats2half2_rn(acc[mb][nb][0], acc[mb][nb][1]);
            __half2 v1 = __floats2half2_rn(acc[mb][nb][2], acc[mb][nb][3]);
            __stcs((unsigned int*)(Yb + (size_t)mrow * HW + noff),
                   *(unsigned int*)&v0);
            __stcs((unsigned int*)(Yb + (size_t)(mrow + 8) * HW + noff),
                   *(unsigned int*)&v1);
        }
    }
}

// ---------------------------------------------------------------------------
// Kernel 2: GroupNorm stats finalize.
// ---------------------------------------------------------------------------
__global__ void __launch_bounds__(128) stats_finalize()
{
    const int id  = blockIdx.x;
    const int tid = threadIdx.x;
    const float* p = g_psum + (size_t)id * 256;

    __shared__ float rs[128], rq[128];
    rs[tid] = p[tid * 2];
    rq[tid] = p[tid * 2 + 1];
    __syncthreads();
    for (int o = 64; o; o >>= 1) {
        if (tid < o) { rs[tid] += rs[tid + o]; rq[tid] += rq[tid + o]; }
        __syncthreads();
    }
    if (tid == 0) {
        const float invN = 1.f / (float)(GSZ * HW);
        float m   = rs[0] * invN;
        float var = rq[0] * invN - m * m;
        g_mean[id] = m;
        g_rstd[id] = rsqrtf(var + EPS);
    }
}

// ---------------------------------------------------------------------------
// Kernel 3: windowed attention (R15 structure + streaming hints on the
// single-use streams: q/k loads __ldcs, xlo residual __ldcs, out __stcs).
// ---------------------------------------------------------------------------
#define QP_ST 72
#define SP_ST 68
#define PH_ST 36
#define KV_ST 36
#define AT_PH   2304
#define AT_KV   4608
#define AT_PMAX 13824
#define AT_PSUM 13952
#define AT_SMEM_BYTES (14080 * 4)

__global__ void __launch_bounds__(256) attn_mma(
    const float* __restrict__ xlo, float* __restrict__ outp,
    const float* __restrict__ gq, const float* __restrict__ bq,
    const float* __restrict__ gk, const float* __restrict__ bk)
{
    extern __shared__ __align__(16) uint32_t sm[];
    uint32_t* sPh = sm + AT_PH;
    uint32_t* sKv = sm + AT_KV;
    float*    pmax = (float*)(sm + AT_PMAX);
    float*    psum = (float*)(sm + AT_PSUM);

    const int tid  = threadIdx.x;
    const int wid  = tid >> 5;
    const int lane = tid & 31;

    const int bb  = blockIdx.x >> 8;
    const int wnd = blockIdx.x & 255;
    const int base_px = ((wnd >> 4) << 3) * 128 + ((wnd & 15) << 3);
    const int wbase = wnd * 64;

    const __half* qb = g_qraw + (size_t)bb * IMG;
    const __half* kb = g_kraw + (size_t)bb * IMG;

    const int wm = wid & 3;
    const int wn = wid >> 2;

    const int p_  = tid >> 4;
    const int pg  = (tid & 15) * 4;

    float acc[4][4];
#pragma unroll
    for (int i = 0; i < 4; i++)
#pragma unroll
        for (int j = 0; j < 4; j++) acc[i][j] = 0.f;

    uint2 q0h, q1h, k0h, k1h;
    {
        const size_t ga0 = (size_t)(2 * p_) * HW + wbase + pg;
        q0h = __ldcs((const uint2*)(qb + ga0));
        q1h = __ldcs((const uint2*)(qb + ga0 + HW));
        k0h = __ldcs((const uint2*)(kb + ga0));
        k1h = __ldcs((const uint2*)(kb + ga0 + HW));
    }

    // ================= Phase S (ping-pong staging, 1 barrier/chunk) =======
#pragma unroll 1
    for (int cc = 0; cc < 8; cc++) {
        uint32_t* sQb = sm + (cc & 1) * 2304;
        uint32_t* sKb = sQb + 1152;

        const int c0 = cc * 32 + 2 * p_;
        const int g  = c0 >> 3;
        float4 q0 = h4_to_f4(q0h), q1 = h4_to_f4(q1h);
        float4 k0 = h4_to_f4(k0h), k1 = h4_to_f4(k1h);
        uint4 tq, tk;
        uint2 kv0, kv1;
        {
            float rq_ = g_rstd[bb * 32 + g], mq_ = g_mean[bb * 32 + g];
            float a0 = rq_ * gq[c0],     d0 = fmaf(-mq_, a0, bq[c0]);
            float a1 = rq_ * gq[c0 + 1], d1 = fmaf(-mq_, a1, bq[c0 + 1]);
            tq.x = pack_h2(fmaf(q0.x, a0, d0), fmaf(q1.x, a1, d1));
            tq.y = pack_h2(fmaf(q0.y, a0, d0), fmaf(q1.y, a1, d1));
            tq.z = pack_h2(fmaf(q0.z, a0, d0), fmaf(q1.z, a1, d1));
            tq.w = pack_h2(fmaf(q0.w, a0, d0), fmaf(q1.w, a1, d1));
        }
        {
            float rk_ = g_rstd[256 + bb * 32 + g], mk_ = g_mean[256 + bb * 32 + g];
            float a0 = rk_ * gk[c0],     d0 = fmaf(-mk_, a0, bk[c0]);
            float a1 = rk_ * gk[c0 + 1], d1 = fmaf(-mk_, a1, bk[c0 + 1]);
            float f00 = fmaf(k0.x, a0, d0), f01 = fmaf(k0.y, a0, d0);
            float f02 = fmaf(k0.z, a0, d0), f03 = fmaf(k0.w, a0, d0);
            float f10 = fmaf(k1.x, a1, d1), f11 = fmaf(k1.y, a1, d1);
            float f12 = fmaf(k1.z, a1, d1), f13 = fmaf(k1.w, a1, d1);
            tk.x = pack_h2(f00, f10);
            tk.y = pack_h2(f01, f11);
            tk.z = pack_h2(f02, f12);
            tk.w = pack_h2(f03, f13);
            kv0 = make_uint2(pack_h2(f00, f01), pack_h2(f02, f03));
            kv1 = make_uint2(pack_h2(f10, f11), pack_h2(f12, f13));
        }

        if (cc < 7) {
            const size_t gan = (size_t)((cc + 1) * 32 + 2 * p_) * HW + wbase + pg;
            q0h = __ldcs((const uint2*)(qb + gan));
            q1h = __ldcs((const uint2*)(qb + gan + HW));
            k0h = __ldcs((const uint2*)(kb + gan));
            k1h = __ldcs((const uint2*)(kb + gan + HW));
        }

        *(uint4*)&sQb[p_ * QP_ST + pg] = tq;
        *(uint4*)&sKb[p_ * QP_ST + pg] = tk;
        *(uint2*)&sKv[(size_t)c0 * KV_ST + (pg >> 1)]       = kv0;
        *(uint2*)&sKv[(size_t)(c0 + 1) * KV_ST + (pg >> 1)] = kv1;
        __syncthreads();

#pragma unroll
        for (int ks = 0; ks < 2; ks++) {
            const int kp = ks * 8 + (lane & 3);
            const int mrow = wm * 16 + (lane >> 2);
            uint32_t a[4];
            a[0] = sQb[kp * QP_ST + mrow];
            a[1] = sQb[kp * QP_ST + mrow + 8];
            a[2] = sQb[(kp + 4) * QP_ST + mrow];
            a[3] = sQb[(kp + 4) * QP_ST + mrow + 8];
#pragma unroll
            for (int nb = 0; nb < 4; nb++) {
                const int ncol = wn * 32 + nb * 8 + (lane >> 2);
                uint32_t b0 = sKb[kp * QP_ST + ncol];
                uint32_t b1 = sKb[(kp + 4) * QP_ST + ncol];
                mmaf16(acc[nb], a, b0, b1);
            }
        }
    }

    // ================= register softmax =================
    const int rA = wm * 16 + (lane >> 2);
    const int rB = rA + 8;
    {
#pragma unroll
        for (int nb = 0; nb < 4; nb++)
#pragma unroll
            for (int r = 0; r < 4; r++) acc[nb][r] *= 0.0625f;

        float mA = acc[0][0], mB = acc[0][2];
#pragma unroll
        for (int nb = 0; nb < 4; nb++) {
            mA = fmaxf(mA, fmaxf(acc[nb][0], acc[nb][1]));
            mB = fmaxf(mB, fmaxf(acc[nb][2], acc[nb][3]));
        }
        mA = fmaxf(mA, __shfl_xor_sync(0xffffffffu, mA, 1));
        mA = fmaxf(mA, __shfl_xor_sync(0xffffffffu, mA, 2));
        mB = fmaxf(mB, __shfl_xor_sync(0xffffffffu, mB, 1));
        mB = fmaxf(mB, __shfl_xor_sync(0xffffffffu, mB, 2));
        __syncthreads();
        if ((lane & 3) == 0) {
            pmax[rA * 2 + wn] = mA;
            pmax[rB * 2 + wn] = mB;
        }
        __syncthreads();

        float MA = fmaxf(pmax[rA * 2], pmax[rA * 2 + 1]);
        float MB = fmaxf(pmax[rB * 2], pmax[rB * 2 + 1]);
        float sA = 0.f, sB = 0.f;
#pragma unroll
        for (int nb = 0; nb < 4; nb++) {
            acc[nb][0] = __expf(acc[nb][0] - MA);
            acc[nb][1] = __expf(acc[nb][1] - MA);
            acc[nb][2] = __expf(acc[nb][2] - MB);
            acc[nb][3] = __expf(acc[nb][3] - MB);
            sA += acc[nb][0] + acc[nb][1];
            sB += acc[nb][2] + acc[nb][3];
        }
        sA += __shfl_xor_sync(0xffffffffu, sA, 1);
        sA += __shfl_xor_sync(0xffffffffu, sA, 2);
        sB += __shfl_xor_sync(0xffffffffu, sB, 1);
        sB += __shfl_xor_sync(0xffffffffu, sB, 2);
        if ((lane & 3) == 0) {
            psum[rA * 2 + wn] = sA;
            psum[rB * 2 + wn] = sB;
        }
        __syncthreads();

        float invA = 1.f / (psum[rA * 2] + psum[rA * 2 + 1]);
        float invB = 1.f / (psum[rB * 2] + psum[rB * 2 + 1]);
#pragma unroll
        for (int nb = 0; nb < 4; nb++) {
            int pcol = wn * 16 + nb * 4 + (lane & 3);
            sPh[rA * PH_ST + pcol] = pack_h2(acc[nb][0] * invA, acc[nb][1] * invA);
            sPh[rB * PH_ST + pcol] = pack_h2(acc[nb][2] * invB, acc[nb][3] * invB);
        }
    }
    __syncthreads();

    // ================= Phase PV =================
    float* sO = (float*)sm;

    const int xc0 = tid >> 4;
    const int xr0 = tid & 15;
    const int xc1 = 16 + xc0;
    float4 xA, xB;
    {
        size_t ga = (size_t)bb * IMG + base_px +
                    (size_t)(xr0 >> 1) * 128 + (xr0 & 1) * 4;
        xA = __ldcs((const float4*)(xlo + ga + (size_t)xc0 * HW));
        xB = __ldcs((const float4*)(xlo + ga + (size_t)xc1 * HW));
    }

#pragma unroll 1
    for (int cc = 0; cc < 8; cc++) {
        float acc2[2][4];
#pragma unroll
        for (int nb = 0; nb < 2; nb++)
#pragma unroll
            for (int r = 0; r < 4; r++) acc2[nb][r] = 0.f;

#pragma unroll
        for (int ks = 0; ks < 4; ks++) {
            const int jp = ks * 8 + (lane & 3);
            const int i0 = wm * 16 + (lane >> 2);
            uint32_t a[4];
            a[0] = sPh[i0 * PH_ST + jp];
            a[1] = sPh[(i0 + 8) * PH_ST + jp];
            a[2] = sPh[i0 * PH_ST + jp + 4];
            a[3] = sPh[(i0 + 8) * PH_ST + jp + 4];
#pragma unroll
            for (int nb = 0; nb < 2; nb++) {
                const int c = cc * 32 + wn * 16 + nb * 8 + (lane >> 2);
                uint32_t b0 = sKv[c * KV_ST + jp];
                uint32_t b1 = sKv[c * KV_ST + jp + 4];
                mmaf16(acc2[nb], a, b0, b1);
            }
        }

        __syncthreads();

        {
            const int px = wm * 16 + (lane >> 2);
#pragma unroll
            for (int nb = 0; nb < 2; nb++) {
                const int chl = wn * 16 + nb * 8 + (lane & 3) * 2;
                sO[chl * SP_ST + px]           = acc2[nb][0];
                sO[(chl + 1) * SP_ST + px]     = acc2[nb][1];
                sO[chl * SP_ST + px + 8]       = acc2[nb][2];
                sO[(chl + 1) * SP_ST + px + 8] = acc2[nb][3];
            }
        }
        __syncthreads();

        {
            size_t gbase = (size_t)bb * IMG + base_px +
                           (size_t)(xr0 >> 1) * 128 + (xr0 & 1) * 4;
            int so_off = (xr0 >> 1) * 8 + (xr0 & 1) * 4;
            float4 o0 = *(const float4*)&sO[xc0 * SP_ST + so_off];
            float4 o1 = *(const float4*)&sO[xc1 * SP_ST + so_off];
            o0.x += xA.x; o0.y += xA.y; o0.z += xA.z; o0.w += xA.w;
            o1.x += xB.x; o1.y += xB.y; o1.z += xB.z; o1.w += xB.w;
            __stcs((float4*)(outp + gbase + (size_t)(cc * 32 + xc0) * HW), o0);
            __stcs((float4*)(outp + gbase + (size_t)(cc * 32 + xc1) * HW), o1);
            if (cc < 7) {
                xA = __ldcs((const float4*)(xlo + gbase +
                            (size_t)((cc + 1) * 32 + xc0) * HW));
                xB = __ldcs((const float4*)(xlo + gbase +
                            (size_t)((cc + 1) * 32 + xc1) * HW));
            }
        }
    }
}

// ---------------------------------------------------------------------------
// Launcher
// ---------------------------------------------------------------------------
extern "C" void kernel_launch(void* const* d_in, const int* in_sizes, int n_in,
                              void* d_out, int out_size)
{
    const float* x_low  = (const float*)d_in[0];
    const float* x_high = (const float*)d_in[1];
    const float* wq     = (const float*)d_in[2];
    const float* wk     = (const float*)d_in[3];
    const float* gq     = (const float*)d_in[4];
    const float* bq     = (const float*)d_in[5];
    const float* gk     = (const float*)d_in[6];
    const float* bk     = (const float*)d_in[7];
    float* outp = (float*)d_out;

    prep_afrag<<<256, 256>>>(wq, wk);

    cudaFuncSetAttribute(proj_mma,
                         cudaFuncAttributeMaxDynamicSharedMemorySize,
                         PJ_SMEM_BYTES);
    proj_mma<<<dim3(2, 1024, 2), 256, PJ_SMEM_BYTES>>>(x_low, x_high);

    stats_finalize<<<512, 128>>>();

    cudaFuncSetAttribute(attn_mma,
                         cudaFuncAttributeMaxDynamicSharedMemorySize,
                         AT_SMEM_BYTES);
    attn_mma<<<2048, 256, AT_SMEM_BYTES>>>(x_low, outp, gq, bq, gk, bk);
}

// round 17
// speedup vs baseline: 1.1674x; 1.0131x over previous
#include <cuda_runtime.h>
#include <cuda_fp16.h>
#include <cstdint>

// ---------------------------------------------------------------------------
// Problem constants
// ---------------------------------------------------------------------------
#define BATCH   8
#define CH      256
#define HW      16384
#define IMG     (CH * HW)
#define GROUPS  32
#define GSZ     (CH / GROUPS)
#define NPIX    64
#define EPS     1e-5f

// g_qraw/g_kraw: fp16, WINDOW-TILED pixel layout within each channel:
//   px' = window_id * 64 + (y&7)*8 + (x&7),  window_id = (y>>3)*16 + (x>>3)
static __device__ __half g_qraw[(size_t)BATCH * IMG];
static __device__ __half g_kraw[(size_t)BATCH * IMG];
static __device__ float g_mean[2 * BATCH * GROUPS];
static __device__ float g_rstd[2 * BATCH * GROUPS];
// Pre-permuted fp16 A fragments (half2 k-pairs, m16n8k16 layout)
static __device__ uint32_t g_afragh[65536];
// per-(tensor,batch,group) x per-pixel-tile partial (sum, sumsq)
static __device__ float g_psum[512 * 256];

// ---------------------------------------------------------------------------
// helpers
// ---------------------------------------------------------------------------
__device__ __forceinline__ uint32_t pack_h2(float x, float y) {
    __half2 h = __float22half2_rn(make_float2(x, y));
    return *(uint32_t*)&h;
}
__device__ __forceinline__ float4 h4_to_f4(uint2 v) {
    float2 a = __half22float2(*(__half2*)&v.x);
    float2 b = __half22float2(*(__half2*)&v.y);
    return make_float4(a.x, a.y, b.x, b.y);
}

__device__ __forceinline__ void mmaf16(float d[4], const uint32_t a[4],
                                       uint32_t b0, uint32_t b1) {
    asm volatile(
        "mma.sync.aligned.m16n8k16.row.col.f32.f16.f16.f32 "
        "{%0,%1,%2,%3}, {%4,%5,%6,%7}, {%8,%9}, {%0,%1,%2,%3};"
        : "+f"(d[0]), "+f"(d[1]), "+f"(d[2]), "+f"(d[3])
        : "r"(a[0]), "r"(a[1]), "r"(a[2]), "r"(a[3]), "r"(b0), "r"(b1));
}

__device__ __forceinline__ uint32_t smem_u32(const void* p) {
    uint32_t a;
    asm("{ .reg .u64 t; cvta.to.shared.u64 t, %1; cvt.u32.u64 %0, t; }"
        : "=r"(a) : "l"(p));
    return a;
}

__device__ __forceinline__ void cpa16(uint32_t dst, const void* src) {
    asm volatile("cp.async.cg.shared.global [%0], [%1], 16;"
                 :: "r"(dst), "l"(src));
}
#define CPA_COMMIT() asm volatile("cp.async.commit_group;" ::: "memory")
#define CPA_WAIT(N)  asm volatile("cp.async.wait_group %0;" :: "n"(N) : "memory")

// ---------------------------------------------------------------------------
// Kernel 0: build fragment-ordered fp16 A operand (half2 k-pairs).
// ---------------------------------------------------------------------------
__global__ void __launch_bounds__(256) prep_afrag(
    const float* __restrict__ wq, const float* __restrict__ wk)
{
    int idx = blockIdx.x * 256 + threadIdx.x;   // 0..65535
    int reg   = idx & 3;
    int lane  = (idx >> 2) & 31;
    int ks    = (idx >> 7) & 1;
    int mbg   = (idx >> 8) & 7;
    int chunk = (idx >> 11) & 7;
    int mt    = (idx >> 14) & 1;
    int t     = (idx >> 15) & 1;

    int m  = mt * 128 + mbg * 16 + (reg & 1) * 8 + (lane >> 2);
    int kp = (lane & 3) + ((reg >> 1) & 1) * 4;
    int k  = chunk * 32 + ks * 16 + kp * 2;
    const float* W = t ? wk : wq;
    g_afragh[idx] = pack_h2(W[m * CH + k], W[m * CH + k + 1]);
}

// ---------------------------------------------------------------------------
// Kernel 1: projection GEMM via fp16 m16n8k16 + fused GroupNorm partials.
// (identical to R16)
// ---------------------------------------------------------------------------
#define BF_ST 132
#define PJ_B  8192
#define PJ_SMEM_BYTES ((8192 + 4 * 4224) * 4)   // 100,352 bytes

__global__ void __launch_bounds__(256, 2) proj_mma(
    const float* __restrict__ xlo, const float* __restrict__ xhi)
{
    extern __shared__ __align__(16) uint32_t smu[];
    const uint32_t sbase = smem_u32(smu);

    const int tid  = threadIdx.x;
    const int wid  = tid >> 5;
    const int lane = tid & 31;

    const int mt = blockIdx.x;
    const int tz = blockIdx.z;
    const float* X = tz ? xhi : xlo;
    __half*      Y = tz ? g_kraw : g_qraw;

    const int bb = blockIdx.y >> 7;
    const int yrow = blockIdx.y & 127;
    const int p0 = yrow << 7;
    const int m0 = mt << 7;

    const float* Xb = X + (size_t)bb * IMG + p0;
    const uint32_t* Agh = g_afragh + (size_t)(tz * 2 + mt) * 16384;

    const int wm = wid >> 2;
    const int wn = wid & 3;

    float acc[4][4][4];
#pragma unroll
    for (int i = 0; i < 4; i++)
#pragma unroll
        for (int j = 0; j < 4; j++)
#pragma unroll
            for (int r = 0; r < 4; r++) acc[i][j][r] = 0.f;

    // ---- prologue: issue chunks 0..2 (A fragments + raw fp32 B rows) ----
#pragma unroll
    for (int pc = 0; pc < 3; pc++) {
        const uint32_t* Agc = Agh + pc * 2048;
#pragma unroll
        for (int i = 0; i < 2; i++) {
            int idx = i * 256 + tid;
            cpa16(sbase + (pc * 2048 + idx * 4) * 4, Agc + idx * 4);
        }
#pragma unroll
        for (int i = 0; i < 4; i++) {
            int idx = i * 256 + tid;
            int row = idx >> 5, c4 = idx & 31;
            cpa16(sbase + (PJ_B + pc * 4224 + row * BF_ST + c4 * 4) * 4,
                  Xb + (size_t)(pc * 32 + row) * HW + c4 * 4);
        }
        CPA_COMMIT();
    }

#pragma unroll 1
    for (int c = 0; c < 8; c++) {
        if (c < 6)      CPA_WAIT(2);
        else if (c == 6) CPA_WAIT(1);
        else             CPA_WAIT(0);
        __syncthreads();

        if (c < 5) {
            const int sl = (c + 3) & 3;
            const uint32_t* Agc = Agh + (c + 3) * 2048;
#pragma unroll
            for (int i = 0; i < 2; i++) {
                int idx = i * 256 + tid;
                cpa16(sbase + (sl * 2048 + idx * 4) * 4, Agc + idx * 4);
            }
#pragma unroll
            for (int i = 0; i < 4; i++) {
                int idx = i * 256 + tid;
                int row = idx >> 5, c4 = idx & 31;
                cpa16(sbase + (PJ_B + sl * 4224 + row * BF_ST + c4 * 4) * 4,
                      Xb + (size_t)((c + 3) * 32 + row) * HW + c4 * 4);
            }
            CPA_COMMIT();
        }

        const uint32_t* Ab = smu + (c & 3) * 2048;
        const float*    Bf = (const float*)(smu + PJ_B + (c & 3) * 4224);

#pragma unroll
        for (int ks = 0; ks < 2; ks++) {
            uint32_t afr[4][4];
#pragma unroll
            for (int mb = 0; mb < 4; mb++) {
                int mbg = wm * 4 + mb;
                *(uint4*)afr[mb] =
                    *(const uint4*)&Ab[(mbg * 2 + ks) * 128 + lane * 4];
            }
            const int kr2  = (ks * 8 + (lane & 3)) * 2;
            const int ncol = wn * 32 + (lane >> 2);
#pragma unroll
            for (int nb = 0; nb < 4; nb++) {
                const int nc = ncol + nb * 8;
                uint32_t b0 = pack_h2(Bf[kr2 * BF_ST + nc],
                                      Bf[(kr2 + 1) * BF_ST + nc]);
                uint32_t b1 = pack_h2(Bf[(kr2 + 8) * BF_ST + nc],
                                      Bf[(kr2 + 9) * BF_ST + nc]);
#pragma unroll
                for (int mb = 0; mb < 4; mb++)
                    mmaf16(acc[mb][nb], afr[mb], b0, b1);
            }
        }
    }

    // ---- fused GroupNorm partial statistics ----
    __shared__ float red[16][4][2];
#pragma unroll
    for (int mb = 0; mb < 4; mb++) {
        float sE = 0.f, qE = 0.f, sO_ = 0.f, qO = 0.f;
#pragma unroll
        for (int nb = 0; nb < 4; nb++) {
            sE += acc[mb][nb][0] + acc[mb][nb][1];
            qE += acc[mb][nb][0] * acc[mb][nb][0] + acc[mb][nb][1] * acc[mb][nb][1];
            sO_ += acc[mb][nb][2] + acc[mb][nb][3];
            qO += acc[mb][nb][2] * acc[mb][nb][2] + acc[mb][nb][3] * acc[mb][nb][3];
        }
#pragma unroll
        for (int off = 16; off; off >>= 1) {
            sE += __shfl_xor_sync(0xffffffffu, sE, off);
            qE += __shfl_xor_sync(0xffffffffu, qE, off);
            sO_ += __shfl_xor_sync(0xffffffffu, sO_, off);
            qO += __shfl_xor_sync(0xffffffffu, qO, off);
        }
        if (lane == 0) {
            int gl = wm * 8 + mb * 2;
            red[gl][wn][0] = sE;     red[gl][wn][1] = qE;
            red[gl + 1][wn][0] = sO_; red[gl + 1][wn][1] = qO;
        }
    }
    __syncthreads();
    if (tid < 32) {
        int gl = tid >> 1, sq = tid & 1;
        float v = red[gl][0][sq] + red[gl][1][sq] + red[gl][2][sq] + red[gl][3][sq];
        g_psum[((size_t)((tz * 8 + bb) * 32) + mt * 16 + gl) * 256 + yrow * 2 + sq] = v;
    }

    // ---- epilogue: fp16 window-tiled store (streaming) ----
    const int base2 = (yrow >> 3) * 1024 + (yrow & 7) * 8;
    __half* Yb = Y + (size_t)bb * IMG + base2;
    const int rl = lane >> 2;
    const int cl = (lane & 3) * 2;
#pragma unroll
    for (int mb = 0; mb < 4; mb++) {
        int mrow = m0 + wm * 64 + mb * 16 + rl;
#pragma unroll
        for (int nb = 0; nb < 4; nb++) {
            int noff = (wn * 4 + nb) * 64 + cl;
            __half2 v0 = __floats2half2_rn(acc[mb][nb][0], acc[mb][nb][1]);
            __half2 v1 = __floats2half2_rn(acc[mb][nb][2], acc[mb][nb][3]);
            __stcs((unsigned int*)(Yb + (size_t)mrow * HW + noff),
                   *(unsigned int*)&v0);
            __stcs((unsigned int*)(Yb + (size_t)(mrow + 8) * HW + noff),
                   *(unsigned int*)&v1);
        }
    }
}

// ---------------------------------------------------------------------------
// Kernel 2: GroupNorm stats finalize.
// ---------------------------------------------------------------------------
__global__ void __launch_bounds__(128) stats_finalize()
{
    const int id  = blockIdx.x;
    const int tid = threadIdx.x;
    const float* p = g_psum + (size_t)id * 256;

    __shared__ float rs[128], rq[128];
    rs[tid] = p[tid * 2];
    rq[tid] = p[tid * 2 + 1];
    __syncthreads();
    for (int o = 64; o; o >>= 1) {
        if (tid < o) { rs[tid] += rs[tid + o]; rq[tid] += rq[tid + o]; }
        __syncthreads();
    }
    if (tid == 0) {
        const float invN = 1.f / (float)(GSZ * HW);
        float m   = rs[0] * invN;
        float var = rq[0] * invN - m * m;
        g_mean[id] = m;
        g_rstd[id] = rsqrtf(var + EPS);
    }
}

// ---------------------------------------------------------------------------
// Kernel 3: windowed attention. R16 + PV A-fragments hoisted to registers
// (sPh is constant through PV; the sO alias prevented compiler hoisting).
// ---------------------------------------------------------------------------
#define QP_ST 72
#define SP_ST 68
#define PH_ST 36
#define KV_ST 36
#define AT_PH   2304
#define AT_KV   4608
#define AT_PMAX 13824
#define AT_PSUM 13952
#define AT_SMEM_BYTES (14080 * 4)

__global__ void __launch_bounds__(256) attn_mma(
    const float* __restrict__ xlo, float* __restrict__ outp,
    const float* __restrict__ gq, const float* __restrict__ bq,
    const float* __restrict__ gk, const float* __restrict__ bk)
{
    extern __shared__ __align__(16) uint32_t sm[];
    uint32_t* sPh = sm + AT_PH;
    uint32_t* sKv = sm + AT_KV;
    float*    pmax = (float*)(sm + AT_PMAX);
    float*    psum = (float*)(sm + AT_PSUM);

    const int tid  = threadIdx.x;
    const int wid  = tid >> 5;
    const int lane = tid & 31;

    const int bb  = blockIdx.x >> 8;
    const int wnd = blockIdx.x & 255;
    const int base_px = ((wnd >> 4) << 3) * 128 + ((wnd & 15) << 3);
    const int wbase = wnd * 64;

    const __half* qb = g_qraw + (size_t)bb * IMG;
    const __half* kb = g_kraw + (size_t)bb * IMG;

    const int wm = wid & 3;
    const int wn = wid >> 2;

    const int p_  = tid >> 4;
    const int pg  = (tid & 15) * 4;

    float acc[4][4];
#pragma unroll
    for (int i = 0; i < 4; i++)
#pragma unroll
        for (int j = 0; j < 4; j++) acc[i][j] = 0.f;

    uint2 q0h, q1h, k0h, k1h;
    {
        const size_t ga0 = (size_t)(2 * p_) * HW + wbase + pg;
        q0h = __ldcs((const uint2*)(qb + ga0));
        q1h = __ldcs((const uint2*)(qb + ga0 + HW));
        k0h = __ldcs((const uint2*)(kb + ga0));
        k1h = __ldcs((const uint2*)(kb + ga0 + HW));
    }

    // ================= Phase S (ping-pong staging, 1 barrier/chunk) =======
#pragma unroll 1
    for (int cc = 0; cc < 8; cc++) {
        uint32_t* sQb = sm + (cc & 1) * 2304;
        uint32_t* sKb = sQb + 1152;

        const int c0 = cc * 32 + 2 * p_;
        const int g  = c0 >> 3;
        float4 q0 = h4_to_f4(q0h), q1 = h4_to_f4(q1h);
        float4 k0 = h4_to_f4(k0h), k1 = h4_to_f4(k1h);
        uint4 tq, tk;
        uint2 kv0, kv1;
        {
            float rq_ = g_rstd[bb * 32 + g], mq_ = g_mean[bb * 32 + g];
            float a0 = rq_ * gq[c0],     d0 = fmaf(-mq_, a0, bq[c0]);
            float a1 = rq_ * gq[c0 + 1], d1 = fmaf(-mq_, a1, bq[c0 + 1]);
            tq.x = pack_h2(fmaf(q0.x, a0, d0), fmaf(q1.x, a1, d1));
            tq.y = pack_h2(fmaf(q0.y, a0, d0), fmaf(q1.y, a1, d1));
            tq.z = pack_h2(fmaf(q0.z, a0, d0), fmaf(q1.z, a1, d1));
            tq.w = pack_h2(fmaf(q0.w, a0, d0), fmaf(q1.w, a1, d1));
        }
        {
            float rk_ = g_rstd[256 + bb * 32 + g], mk_ = g_mean[256 + bb * 32 + g];
            float a0 = rk_ * gk[c0],     d0 = fmaf(-mk_, a0, bk[c0]);
            float a1 = rk_ * gk[c0 + 1], d1 = fmaf(-mk_, a1, bk[c0 + 1]);
            float f00 = fmaf(k0.x, a0, d0), f01 = fmaf(k0.y, a0, d0);
            float f02 = fmaf(k0.z, a0, d0), f03 = fmaf(k0.w, a0, d0);
            float f10 = fmaf(k1.x, a1, d1), f11 = fmaf(k1.y, a1, d1);
            float f12 = fmaf(k1.z, a1, d1), f13 = fmaf(k1.w, a1, d1);
            tk.x = pack_h2(f00, f10);
            tk.y = pack_h2(f01, f11);
            tk.z = pack_h2(f02, f12);
            tk.w = pack_h2(f03, f13);
            kv0 = make_uint2(pack_h2(f00, f01), pack_h2(f02, f03));
            kv1 = make_uint2(pack_h2(f10, f11), pack_h2(f12, f13));
        }

        if (cc < 7) {
            const size_t gan = (size_t)((cc + 1) * 32 + 2 * p_) * HW + wbase + pg;
            q0h = __ldcs((const uint2*)(qb + gan));
            q1h = __ldcs((const uint2*)(qb + gan + HW));
            k0h = __ldcs((const uint2*)(kb + gan));
            k1h = __ldcs((const uint2*)(kb + gan + HW));
        }

        *(uint4*)&sQb[p_ * QP_ST + pg] = tq;
        *(uint4*)&sKb[p_ * QP_ST + pg] = tk;
        *(uint2*)&sKv[(size_t)c0 * KV_ST + (pg >> 1)]       = kv0;
        *(uint2*)&sKv[(size_t)(c0 + 1) * KV_ST + (pg >> 1)] = kv1;
        __syncthreads();

#pragma unroll
        for (int ks = 0; ks < 2; ks++) {
            const int kp = ks * 8 + (lane & 3);
            const int mrow = wm * 16 + (lane >> 2);
            uint32_t a[4];
            a[0] = sQb[kp * QP_ST + mrow];
            a[1] = sQb[kp * QP_ST + mrow + 8];
            a[2] = sQb[(kp + 4) * QP_ST + mrow];
            a[3] = sQb[(kp + 4) * QP_ST + mrow + 8];
#pragma unroll
            for (int nb = 0; nb < 4; nb++) {
                const int ncol = wn * 32 + nb * 8 + (lane >> 2);
                uint32_t b0 = sKb[kp * QP_ST + ncol];
                uint32_t b1 = sKb[(kp + 4) * QP_ST + ncol];
                mmaf16(acc[nb], a, b0, b1);
            }
        }
    }

    // ================= register softmax =================
    const int rA = wm * 16 + (lane >> 2);
    const int rB = rA + 8;
    {
#pragma unroll
        for (int nb = 0; nb < 4; nb++)
#pragma unroll
            for (int r = 0; r < 4; r++) acc[nb][r] *= 0.0625f;

        float mA = acc[0][0], mB = acc[0][2];
#pragma unroll
        for (int nb = 0; nb < 4; nb++) {
            mA = fmaxf(mA, fmaxf(acc[nb][0], acc[nb][1]));
            mB = fmaxf(mB, fmaxf(acc[nb][2], acc[nb][3]));
        }
        mA = fmaxf(mA, __shfl_xor_sync(0xffffffffu, mA, 1));
        mA = fmaxf(mA, __shfl_xor_sync(0xffffffffu, mA, 2));
        mB = fmaxf(mB, __shfl_xor_sync(0xffffffffu, mB, 1));
        mB = fmaxf(mB, __shfl_xor_sync(0xffffffffu, mB, 2));
        __syncthreads();
        if ((lane & 3) == 0) {
            pmax[rA * 2 + wn] = mA;
            pmax[rB * 2 + wn] = mB;
        }
        __syncthreads();

        float MA = fmaxf(pmax[rA * 2], pmax[rA * 2 + 1]);
        float MB = fmaxf(pmax[rB * 2], pmax[rB * 2 + 1]);
        float sA = 0.f, sB = 0.f;
#pragma unroll
        for (int nb = 0; nb < 4; nb++) {
            acc[nb][0] = __expf(acc[nb][0] - MA);
            acc[nb][1] = __expf(acc[nb][1] - MA);
            acc[nb][2] = __expf(acc[nb][2] - MB);
            acc[nb][3] = __expf(acc[nb][3] - MB);
            sA += acc[nb][0] + acc[nb][1];
            sB += acc[nb][2] + acc[nb][3];
        }
        sA += __shfl_xor_sync(0xffffffffu, sA, 1);
        sA += __shfl_xor_sync(0xffffffffu, sA, 2);
        sB += __shfl_xor_sync(0xffffffffu, sB, 1);
        sB += __shfl_xor_sync(0xffffffffu, sB, 2);
        if ((lane & 3) == 0) {
            psum[rA * 2 + wn] = sA;
            psum[rB * 2 + wn] = sB;
        }
        __syncthreads();

        float invA = 1.f / (psum[rA * 2] + psum[rA * 2 + 1]);
        float invB = 1.f / (psum[rB * 2] + psum[rB * 2 + 1]);
#pragma unroll
        for (int nb = 0; nb < 4; nb++) {
            int pcol = wn * 16 + nb * 4 + (lane & 3);
            sPh[rA * PH_ST + pcol] = pack_h2(acc[nb][0] * invA, acc[nb][1] * invA);
            sPh[rB * PH_ST + pcol] = pack_h2(acc[nb][2] * invB, acc[nb][3] * invB);
        }
    }
    __syncthreads();

    // ================= Phase PV =================
    float* sO = (float*)sm;

    // Hoist ALL P fragments for this warp into registers (sPh constant in PV)
    uint32_t pa[4][4];
    {
        const int i0 = wm * 16 + (lane >> 2);
#pragma unroll
        for (int ks = 0; ks < 4; ks++) {
            const int jp = ks * 8 + (lane & 3);
            pa[ks][0] = sPh[i0 * PH_ST + jp];
            pa[ks][1] = sPh[(i0 + 8) * PH_ST + jp];
            pa[ks][2] = sPh[i0 * PH_ST + jp + 4];
            pa[ks][3] = sPh[(i0 + 8) * PH_ST + jp + 4];
        }
    }

    const int xc0 = tid >> 4;
    const int xr0 = tid & 15;
    const int xc1 = 16 + xc0;
    float4 xA, xB;
    {
        size_t ga = (size_t)bb * IMG + base_px +
                    (size_t)(xr0 >> 1) * 128 + (xr0 & 1) * 4;
        xA = __ldcs((const float4*)(xlo + ga + (size_t)xc0 * HW));
        xB = __ldcs((const float4*)(xlo + ga + (size_t)xc1 * HW));
    }

#pragma unroll 1
    for (int cc = 0; cc < 8; cc++) {
        float acc2[2][4];
#pragma unroll
        for (int nb = 0; nb < 2; nb++)
#pragma unroll
            for (int r = 0; r < 4; r++) acc2[nb][r] = 0.f;

#pragma unroll
        for (int ks = 0; ks < 4; ks++) {
            const int jp = ks * 8 + (lane & 3);
#pragma unroll
            for (int nb = 0; nb < 2; nb++) {
                const int c = cc * 32 + wn * 16 + nb * 8 + (lane >> 2);
                uint32_t b0 = sKv[c * KV_ST + jp];
                uint32_t b1 = sKv[c * KV_ST + jp + 4];
                mmaf16(acc2[nb], pa[ks], b0, b1);
            }
        }

        __syncthreads();

        {
            const int px = wm * 16 + (lane >> 2);
#pragma unroll
            for (int nb = 0; nb < 2; nb++) {
                const int chl = wn * 16 + nb * 8 + (lane & 3) * 2;
                sO[chl * SP_ST + px]           = acc2[nb][0];
                sO[(chl + 1) * SP_ST + px]     = acc2[nb][1];
                sO[chl * SP_ST + px + 8]       = acc2[nb][2];
                sO[(chl + 1) * SP_ST + px + 8] = acc2[nb][3];
            }
        }
        __syncthreads();

        {
            size_t gbase = (size_t)bb * IMG + base_px +
                           (size_t)(xr0 >> 1) * 128 + (xr0 & 1) * 4;
            int so_off = (xr0 >> 1) * 8 + (xr0 & 1) * 4;
            float4 o0 = *(const float4*)&sO[xc0 * SP_ST + so_off];
            float4 o1 = *(const float4*)&sO[xc1 * SP_ST + so_off];
            o0.x += xA.x; o0.y += xA.y; o0.z += xA.z; o0.w += xA.w;
            o1.x += xB.x; o1.y += xB.y; o1.z += xB.z; o1.w += xB.w;
            __stcs((float4*)(outp + gbase + (size_t)(cc * 32 + xc0) * HW), o0);
            __stcs((float4*)(outp + gbase + (size_t)(cc * 32 + xc1) * HW), o1);
            if (cc < 7) {
                xA = __ldcs((const float4*)(xlo + gbase +
                            (size_t)((cc + 1) * 32 + xc0) * HW));
                xB = __ldcs((const float4*)(xlo + gbase +
                            (size_t)((cc + 1) * 32 + xc1) * HW));
            }
        }
    }
}

// ---------------------------------------------------------------------------
// Launcher
// ---------------------------------------------------------------------------
extern "C" void kernel_launch(void* const* d_in, const int* in_sizes, int n_in,
                              void* d_out, int out_size)
{
    const float* x_low  = (const float*)d_in[0];
    const float* x_high = (const float*)d_in[1];
    const float* wq     = (const float*)d_in[2];
    const float* wk     = (const float*)d_in[3];
    const float* gq     = (const float*)d_in[4];
    const float* bq     = (const float*)d_in[5];
    const float* gk     = (const float*)d_in[6];
    const float* bk     = (const float*)d_in[7];
    float* outp = (float*)d_out;

    prep_afrag<<<256, 256>>>(wq, wk);

    cudaFuncSetAttribute(proj_mma,
                         cudaFuncAttributeMaxDynamicSharedMemorySize,
                         PJ_SMEM_BYTES);
    proj_mma<<<dim3(2, 1024, 2), 256, PJ_SMEM_BYTES>>>(x_low, x_high);

    stats_finalize<<<512, 128>>>();

    cudaFuncSetAttribute(attn_mma,
                         cudaFuncAttributeMaxDynamicSharedMemorySize,
                         AT_SMEM_BYTES);
    attn_mma<<<2048, 256, AT_SMEM_BYTES>>>(x_low, outp, gq, bq, gk, bk);
}